// round 1
// baseline (speedup 1.0000x reference)
#include <cuda_runtime.h>
#include <cstdint>
#include <cstddef>

// Problem constants
#define Bb   16
#define Cc   128
#define Hh   64
#define Ww   64
#define NHh  8
#define HDd  16
#define HW   4096          // H*W
#define OUTC 512

// ---------------------------------------------------------------------------
// Scratch (static device globals — no allocation allowed)
// ---------------------------------------------------------------------------
__device__ float g_s[Bb * Cc * HW];            // CPE output (B,C,H,W)        32 MB
__device__ float g_qkv[Bb * 3 * Cc * HW];      // QKV (B,3C,H,W)              96 MB
__device__ float g_lambda[Bb * NHh * HDd * HDd]; // scaled content lambda
__device__ float g_pool[Bb * Cc];
__device__ float g_ca[Bb * Cc];
__device__ float g_w2b[Bb * OUTC * Cc];        // out_w[:,128:] * ca           4 MB
__device__ float g_r1[Bb * Cc * HW];           // result1                      32 MB

// ---------------------------------------------------------------------------
// 1) CPE: s = dwconv3x3(src, cpe_w) + src
// ---------------------------------------------------------------------------
__global__ __launch_bounds__(256) void k_cpe(const float* __restrict__ src,
                                             const float* __restrict__ cpe_w,
                                             float* __restrict__ s) {
    size_t idx = (size_t)blockIdx.x * 256 + threadIdx.x;
    if (idx >= (size_t)Bb * Cc * HW) return;
    int w = idx & 63;
    int h = (idx >> 6) & 63;
    int c = (idx >> 12) & 127;
    float sum = src[idx];
    const float* wp = cpe_w + c * 9;
#pragma unroll
    for (int dy = -1; dy <= 1; dy++) {
#pragma unroll
        for (int dx = -1; dx <= 1; dx++) {
            int hy = h + dy, wx = w + dx;
            if (hy >= 0 && hy < Hh && wx >= 0 && wx < Ww) {
                sum += wp[(dy + 1) * 3 + (dx + 1)] * src[idx + dy * Ww + dx];
            }
        }
    }
    s[idx] = sum;
}

// ---------------------------------------------------------------------------
// 2) Pool: mean over H,W per (b,c)
// ---------------------------------------------------------------------------
__global__ __launch_bounds__(256) void k_pool(const float* __restrict__ src,
                                              float* __restrict__ pool) {
    int bc = blockIdx.x;  // 0..2047
    const float* p = src + (size_t)bc * HW;
    float sum = 0.f;
    for (int n = threadIdx.x; n < HW; n += 256) sum += p[n];
    __shared__ float sm[256];
    sm[threadIdx.x] = sum;
    __syncthreads();
    for (int sstep = 128; sstep > 0; sstep >>= 1) {
        if (threadIdx.x < sstep) sm[threadIdx.x] += sm[threadIdx.x + sstep];
        __syncthreads();
    }
    if (threadIdx.x == 0) pool[bc] = sm[0] * (1.0f / HW);
}

// ---------------------------------------------------------------------------
// 3) ECA channel attention (tiny)
// ---------------------------------------------------------------------------
__global__ void k_eca(const float* __restrict__ pool,
                      const float* __restrict__ conv1d_w,
                      float* __restrict__ ca) {
    int idx = blockIdx.x * 256 + threadIdx.x;
    if (idx >= Bb * Cc) return;
    int c = idx & 127;
    float w0 = conv1d_w[0], w1 = conv1d_w[1], w2 = conv1d_w[2];
    float left  = (c > 0)   ? pool[idx - 1] : 0.f;
    float mid   = pool[idx];
    float right = (c < 127) ? pool[idx + 1] : 0.f;
    float z = w0 * left + w1 * mid + w2 * right;
    ca[idx] = 1.0f / (1.0f + __expf(-z));
}

// ---------------------------------------------------------------------------
// 4) w2b[b][o][c] = out_w[o][128+c] * ca[b][c]
// ---------------------------------------------------------------------------
__global__ __launch_bounds__(256) void k_w2b(const float* __restrict__ out_w,
                                             const float* __restrict__ ca,
                                             float* __restrict__ w2b) {
    int idx = blockIdx.x * 256 + threadIdx.x;
    if (idx >= Bb * OUTC * Cc) return;
    int c = idx & 127;
    int o = (idx >> 7) & 511;
    int b = idx >> 16;
    w2b[idx] = out_w[o * 256 + 128 + c] * ca[(b << 7) + c];
}

// ---------------------------------------------------------------------------
// 5) Generic batched SGEMM: C[b] = sum_p A_p[b] (MxK, row-major lda) @ B_p[b]
//    (K x 4096, row stride 4096). BM=BN=128, BK=8, 8x8/thread.
//    All dims exactly divisible.
// ---------------------------------------------------------------------------
template <int NPARTS>
__global__ __launch_bounds__(256) void k_sgemm(
    const float* __restrict__ A0, size_t sA0, int lda0,
    const float* __restrict__ B0, size_t sB0,
    const float* __restrict__ A1, size_t sA1, int lda1,
    const float* __restrict__ B1, size_t sB1,
    float* __restrict__ C, size_t sC) {
    constexpr int BM = 128, BN = 128, BK = 8;
    const int bz = blockIdx.z;
    const int mtile = blockIdx.y, ntile = blockIdx.x;
    __shared__ float As[BK][BM];
    __shared__ float Bs[BK][BN];
    const int tid = threadIdx.x;
    const int tr = tid >> 4, tc = tid & 15;

    const int arow = tid >> 1;            // 0..127
    const int acol = (tid & 1) * 4;       // 0 or 4
    const int brow = tid >> 5;            // 0..7
    const int bcol = (tid & 31) * 4;      // 0..124

    float acc[8][8];
#pragma unroll
    for (int m = 0; m < 8; m++)
#pragma unroll
        for (int n = 0; n < 8; n++) acc[m][n] = 0.f;

#pragma unroll
    for (int p = 0; p < NPARTS; ++p) {
        const float* A = (p == 0) ? A0 + (size_t)bz * sA0 : A1 + (size_t)bz * sA1;
        const int lda  = (p == 0) ? lda0 : lda1;
        const float* B = (p == 0) ? B0 + (size_t)bz * sB0 : B1 + (size_t)bz * sB1;
        const float* Atile = A + (size_t)(mtile * BM + arow) * lda + acol;
        const float* Btile = B + (size_t)brow * HW + ntile * BN + bcol;

        for (int k0 = 0; k0 < 128; k0 += BK) {
            float4 a4 = *reinterpret_cast<const float4*>(Atile + k0);
            float4 b4 = *reinterpret_cast<const float4*>(Btile + (size_t)k0 * HW);
            As[acol + 0][arow] = a4.x;
            As[acol + 1][arow] = a4.y;
            As[acol + 2][arow] = a4.z;
            As[acol + 3][arow] = a4.w;
            *reinterpret_cast<float4*>(&Bs[brow][bcol]) = b4;
            __syncthreads();
#pragma unroll
            for (int k = 0; k < BK; k++) {
                float ra[8], rb[8];
#pragma unroll
                for (int m = 0; m < 8; m++) ra[m] = As[k][tr * 8 + m];
#pragma unroll
                for (int n = 0; n < 8; n++) rb[n] = Bs[k][tc * 8 + n];
#pragma unroll
                for (int m = 0; m < 8; m++)
#pragma unroll
                    for (int n = 0; n < 8; n++) acc[m][n] += ra[m] * rb[n];
            }
            __syncthreads();
        }
    }

    float* Cp = C + (size_t)bz * sC + (size_t)(mtile * BM + tr * 8) * HW + ntile * BN + tc * 8;
#pragma unroll
    for (int m = 0; m < 8; m++) {
        float4 v0 = make_float4(acc[m][0], acc[m][1], acc[m][2], acc[m][3]);
        float4 v1 = make_float4(acc[m][4], acc[m][5], acc[m][6], acc[m][7]);
        *reinterpret_cast<float4*>(Cp + (size_t)m * HW)     = v0;
        *reinterpret_cast<float4*>(Cp + (size_t)m * HW + 4) = v1;
    }
}

// ---------------------------------------------------------------------------
// 6) Fused softmax(k row) + content lambda (scaled)
//    block = (bh, i).  lambda[bh][i][o] = 0.25 * sum_n softmax(k[i])[n]*v[o][n]
// ---------------------------------------------------------------------------
__global__ __launch_bounds__(256) void k_softmax_lambda(const float* __restrict__ qkv,
                                                        float* __restrict__ lambda) {
    const int bh = blockIdx.x;   // 0..127
    const int i  = blockIdx.y;   // 0..15
    const int b = bh >> 3, nh = bh & 7;
    const float* krow  = qkv + ((size_t)b * 384 + 128 + nh * 16 + i) * HW;
    const float* vbase = qkv + ((size_t)b * 384 + 256 + nh * 16) * HW;
    const int tid = threadIdx.x;

    __shared__ float sm[256];
    // pass 1: max
    float mx = -1e30f;
    for (int n = tid; n < HW; n += 256) mx = fmaxf(mx, krow[n]);
    sm[tid] = mx;
    __syncthreads();
    for (int sstep = 128; sstep > 0; sstep >>= 1) {
        if (tid < sstep) sm[tid] = fmaxf(sm[tid], sm[tid + sstep]);
        __syncthreads();
    }
    mx = sm[0];
    __syncthreads();

    // pass 2: sumexp + 16 v dot products
    float se = 0.f;
    float acc[16];
#pragma unroll
    for (int o = 0; o < 16; o++) acc[o] = 0.f;
    for (int n = tid; n < HW; n += 256) {
        float e = __expf(krow[n] - mx);
        se += e;
#pragma unroll
        for (int o = 0; o < 16; o++) acc[o] += e * vbase[(size_t)o * HW + n];
    }

    __shared__ float red[17][256];
#pragma unroll
    for (int o = 0; o < 16; o++) red[o][tid] = acc[o];
    red[16][tid] = se;
    __syncthreads();
    for (int sstep = 128; sstep > 0; sstep >>= 1) {
        if (tid < sstep) {
#pragma unroll
            for (int v = 0; v < 17; v++) red[v][tid] += red[v][tid + sstep];
        }
        __syncthreads();
    }
    if (tid < 16) {
        float inv = 1.0f / red[16][0];
        lambda[((size_t)bh * 16 + i) * 16 + tid] = 0.25f * red[tid][0] * inv;  // 0.25 = HD^-0.5
    }
}

// ---------------------------------------------------------------------------
// 7) result1 = content_output + q * position_lambda
//    block: one (bh, 16x16 pixel tile); computes all 16 output head-dims.
// ---------------------------------------------------------------------------
__global__ __launch_bounds__(256) void k_result1(const float* __restrict__ qkv,
                                                 const float* __restrict__ lambda,
                                                 const float* __restrict__ rel_pos,
                                                 float* __restrict__ r1) {
    const int bh = blockIdx.z;  // 0..127
    const int b = bh >> 3, nh = bh & 7;
    const int x0 = blockIdx.x * 16, y0 = blockIdx.y * 16;
    const int tid = threadIdx.x;
    const int px = tid & 15, py = tid >> 4;

    __shared__ float lam[16][16];        // [i][o]
    __shared__ float relw[16][25];
    __shared__ float qs[16][16][16];     // [ch][y][x]
    __shared__ float vs[16][20][20];     // [ch][y][x] with 2-halo

    // lambda tile (256 entries)
    lam[py][px] = lambda[((size_t)bh * 16 + py) * 16 + px];
    // rel_pos (400 entries)
    for (int t = tid; t < 400; t += 256) relw[t / 25][t % 25] = rel_pos[t];
    // q tile
    const float* qbase = qkv + ((size_t)b * 384 + nh * 16) * HW;
#pragma unroll
    for (int ch = 0; ch < 16; ch++) {
        qs[ch][py][px] = qbase[(size_t)ch * HW + (y0 + py) * Ww + x0 + px];
    }
    // v halo tile (6400 entries)
    const float* vbase = qkv + ((size_t)b * 384 + 256 + nh * 16) * HW;
    for (int t = tid; t < 6400; t += 256) {
        int ch = t / 400;
        int r = t % 400;
        int vy = r / 20, vx = r % 20;
        int gy = y0 + vy - 2, gx = x0 + vx - 2;
        float val = 0.f;
        if (gy >= 0 && gy < Hh && gx >= 0 && gx < Ww)
            val = vbase[(size_t)ch * HW + gy * Ww + gx];
        vs[ch][vy][vx] = val;
    }
    __syncthreads();

    float* obase = r1 + ((size_t)b * Cc + nh * 16) * HW + (y0 + py) * Ww + x0 + px;
#pragma unroll
    for (int o = 0; o < 16; o++) {
        float content = 0.f;
#pragma unroll
        for (int i = 0; i < 16; i++) content += qs[i][py][px] * lam[i][o];
        float pos = 0.f;
#pragma unroll
        for (int ky = 0; ky < 5; ky++)
#pragma unroll
            for (int kx = 0; kx < 5; kx++)
                pos += relw[o][ky * 5 + kx] * vs[o][py + ky][px + kx];
        obase[(size_t)o * HW] = content + qs[o][py][px] * pos;
    }
}

// ---------------------------------------------------------------------------
// Launch
// ---------------------------------------------------------------------------
extern "C" void kernel_launch(void* const* d_in, const int* in_sizes, int n_in,
                              void* d_out, int out_size) {
    const float* src      = (const float*)d_in[0];
    const float* cpe_w    = (const float*)d_in[1];
    const float* qkv_w    = (const float*)d_in[2];
    const float* rel_pos  = (const float*)d_in[3];
    const float* conv1d_w = (const float*)d_in[4];
    const float* out_w    = (const float*)d_in[5];
    float* out = (float*)d_out;

    float *s_p, *qkv_p, *lam_p, *pool_p, *ca_p, *w2b_p, *r1_p;
    cudaGetSymbolAddress((void**)&s_p,    g_s);
    cudaGetSymbolAddress((void**)&qkv_p,  g_qkv);
    cudaGetSymbolAddress((void**)&lam_p,  g_lambda);
    cudaGetSymbolAddress((void**)&pool_p, g_pool);
    cudaGetSymbolAddress((void**)&ca_p,   g_ca);
    cudaGetSymbolAddress((void**)&w2b_p,  g_w2b);
    cudaGetSymbolAddress((void**)&r1_p,   g_r1);

    // 1) CPE
    k_cpe<<<(Bb * Cc * HW + 255) / 256, 256>>>(src, cpe_w, s_p);
    // 2) Pool + ECA + w2b
    k_pool<<<Bb * Cc, 256>>>(src, pool_p);
    k_eca<<<(Bb * Cc + 255) / 256, 256>>>(pool_p, conv1d_w, ca_p);
    k_w2b<<<(Bb * OUTC * Cc + 255) / 256, 256>>>(out_w, ca_p, w2b_p);
    // 3) QKV GEMM: per batch (384x128)@(128x4096)
    {
        dim3 grid(HW / 128, 3 * Cc / 128, Bb);
        k_sgemm<1><<<grid, 256>>>(qkv_w, 0, Cc,
                                  s_p, (size_t)Cc * HW,
                                  nullptr, 0, 0, nullptr, 0,
                                  qkv_p, (size_t)3 * Cc * HW);
    }
    // 4) softmax + lambda
    {
        dim3 grid(Bb * NHh, HDd);
        k_softmax_lambda<<<grid, 256>>>(qkv_p, lam_p);
    }
    // 5) result1
    {
        dim3 grid(Ww / 16, Hh / 16, Bb * NHh);
        k_result1<<<grid, 256>>>(qkv_p, lam_p, rel_pos, r1_p);
    }
    // 6) output GEMM: out = out_w[:, :128] @ r1  +  w2b @ src
    {
        dim3 grid(HW / 128, OUTC / 128, Bb);
        k_sgemm<2><<<grid, 256>>>(out_w, 0, 2 * Cc,
                                  r1_p, (size_t)Cc * HW,
                                  w2b_p, (size_t)OUTC * Cc, Cc,
                                  src, (size_t)Cc * HW,
                                  out, (size_t)OUTC * HW);
    }
}

// round 2
// speedup vs baseline: 1.2128x; 1.2128x over previous
#include <cuda_runtime.h>
#include <cstdint>
#include <cstddef>

// Problem constants
#define Bb   16
#define Cc   128
#define Hh   64
#define Ww   64
#define NHh  8
#define HDd  16
#define HW   4096          // H*W
#define OUTC 512

// ---------------------------------------------------------------------------
// Scratch (static device globals — no allocation allowed)
// ---------------------------------------------------------------------------
__device__ float g_s[Bb * Cc * HW];              // CPE output (B,C,H,W)
__device__ float g_qkv[Bb * 3 * Cc * HW];        // QKV (B,3C,H,W)
__device__ float g_lambda[Bb * NHh * HDd * HDd]; // scaled content lambda
__device__ float g_pool[Bb * Cc];
__device__ float g_ca[Bb * Cc];
__device__ float g_w2b[Bb * OUTC * Cc];          // out_w[:,128:] * ca
__device__ float g_r1[Bb * Cc * HW];             // result1

// ---------------------------------------------------------------------------
// tf32 helpers
// ---------------------------------------------------------------------------
__device__ __forceinline__ uint32_t f2tf32(float x) {
    uint32_t r;
    asm("cvt.rna.tf32.f32 %0, %1;" : "=r"(r) : "f"(x));
    return r;
}

__device__ __forceinline__ void mma_tf32(float* c, const uint32_t* a, const uint32_t* b) {
    asm volatile(
        "mma.sync.aligned.m16n8k8.row.col.f32.tf32.tf32.f32 "
        "{%0,%1,%2,%3}, {%4,%5,%6,%7}, {%8,%9}, {%0,%1,%2,%3};\n"
        : "+f"(c[0]), "+f"(c[1]), "+f"(c[2]), "+f"(c[3])
        : "r"(a[0]), "r"(a[1]), "r"(a[2]), "r"(a[3]), "r"(b[0]), "r"(b[1]));
}

// ---------------------------------------------------------------------------
// 1) CPE: s = dwconv3x3(src, cpe_w) + src
// ---------------------------------------------------------------------------
__global__ __launch_bounds__(256) void k_cpe(const float* __restrict__ src,
                                             const float* __restrict__ cpe_w,
                                             float* __restrict__ s) {
    size_t idx = (size_t)blockIdx.x * 256 + threadIdx.x;
    if (idx >= (size_t)Bb * Cc * HW) return;
    int w = idx & 63;
    int h = (idx >> 6) & 63;
    int c = (idx >> 12) & 127;
    float sum = src[idx];
    const float* wp = cpe_w + c * 9;
#pragma unroll
    for (int dy = -1; dy <= 1; dy++) {
#pragma unroll
        for (int dx = -1; dx <= 1; dx++) {
            int hy = h + dy, wx = w + dx;
            if (hy >= 0 && hy < Hh && wx >= 0 && wx < Ww) {
                sum += wp[(dy + 1) * 3 + (dx + 1)] * src[idx + dy * Ww + dx];
            }
        }
    }
    s[idx] = sum;
}

// ---------------------------------------------------------------------------
// 2) Pool: mean over H,W per (b,c)
// ---------------------------------------------------------------------------
__global__ __launch_bounds__(256) void k_pool(const float* __restrict__ src,
                                              float* __restrict__ pool) {
    int bc = blockIdx.x;
    const float* p = src + (size_t)bc * HW;
    float sum = 0.f;
    for (int n = threadIdx.x; n < HW; n += 256) sum += p[n];
    __shared__ float sm[256];
    sm[threadIdx.x] = sum;
    __syncthreads();
    for (int sstep = 128; sstep > 0; sstep >>= 1) {
        if (threadIdx.x < sstep) sm[threadIdx.x] += sm[threadIdx.x + sstep];
        __syncthreads();
    }
    if (threadIdx.x == 0) pool[bc] = sm[0] * (1.0f / HW);
}

// ---------------------------------------------------------------------------
// 3) ECA channel attention (tiny)
// ---------------------------------------------------------------------------
__global__ void k_eca(const float* __restrict__ pool,
                      const float* __restrict__ conv1d_w,
                      float* __restrict__ ca) {
    int idx = blockIdx.x * 256 + threadIdx.x;
    if (idx >= Bb * Cc) return;
    int c = idx & 127;
    float w0 = conv1d_w[0], w1 = conv1d_w[1], w2 = conv1d_w[2];
    float left  = (c > 0)   ? pool[idx - 1] : 0.f;
    float mid   = pool[idx];
    float right = (c < 127) ? pool[idx + 1] : 0.f;
    float z = w0 * left + w1 * mid + w2 * right;
    ca[idx] = 1.0f / (1.0f + __expf(-z));
}

// ---------------------------------------------------------------------------
// 4) w2b[b][o][c] = out_w[o][128+c] * ca[b][c]
// ---------------------------------------------------------------------------
__global__ __launch_bounds__(256) void k_w2b(const float* __restrict__ out_w,
                                             const float* __restrict__ ca,
                                             float* __restrict__ w2b) {
    int idx = blockIdx.x * 256 + threadIdx.x;
    if (idx >= Bb * OUTC * Cc) return;
    int c = idx & 127;
    int o = (idx >> 7) & 511;
    int b = idx >> 16;
    w2b[idx] = out_w[o * 256 + 128 + c] * ca[(b << 7) + c];
}

// ---------------------------------------------------------------------------
// 5) Batched tf32 tensor-core GEMM:
//    C[b] = sum_p A_p[b] (M x 128, row-major lda_p) @ B_p[b] (128 x 4096)
//    BM=BN=128, BK=16. 8 warps, each 32x64 via m16n8k8 tf32 mma.
// ---------------------------------------------------------------------------
template <int NPARTS>
__global__ __launch_bounds__(256) void k_mma_gemm(
    const float* __restrict__ A0, size_t sA0, int lda0,
    const float* __restrict__ B0, size_t sB0,
    const float* __restrict__ A1, size_t sA1, int lda1,
    const float* __restrict__ B1, size_t sB1,
    float* __restrict__ C, size_t sC) {
    constexpr int BM = 128, BN = 128, BK = 16;
    constexpr int AST = 20;   // As row stride (words) — conflict-free frag loads
    constexpr int BST = 136;  // Bs row stride (words) — conflict-free frag loads

    __shared__ uint32_t As[2][BM * AST];
    __shared__ uint32_t Bs[2][BK * BST];

    const int tid = threadIdx.x;
    const int bz = blockIdx.z, mtile = blockIdx.y, ntile = blockIdx.x;
    const int warp = tid >> 5, lane = tid & 31;
    const int g = lane >> 2, t = lane & 3;
    const int wm = (warp >> 1) * 32, wn = (warp & 1) * 64;

    float4 ar[2], br[2];

    auto load_tile = [&](int c) {
        const int part = c >> 3;
        const int kin = (c & 7) * BK;
        const float* A = part ? A1 + (size_t)bz * sA1 : A0 + (size_t)bz * sA0;
        const int lda  = part ? lda1 : lda0;
        const float* B = part ? B1 + (size_t)bz * sB1 : B0 + (size_t)bz * sB0;
#pragma unroll
        for (int i = 0; i < 2; i++) {
            int idx = tid * 2 + i;
            int row = idx >> 2, kq = (idx & 3) * 4;
            ar[i] = *reinterpret_cast<const float4*>(
                A + (size_t)(mtile * BM + row) * lda + kin + kq);
            int kk = idx >> 5, col = (idx & 31) * 4;
            br[i] = *reinterpret_cast<const float4*>(
                B + (size_t)(kin + kk) * HW + ntile * BN + col);
        }
    };

    auto store_tile = [&](int buf) {
#pragma unroll
        for (int i = 0; i < 2; i++) {
            int idx = tid * 2 + i;
            int row = idx >> 2, kq = (idx & 3) * 4;
            uint32_t* ap = &As[buf][row * AST + kq];
            ap[0] = f2tf32(ar[i].x);
            ap[1] = f2tf32(ar[i].y);
            ap[2] = f2tf32(ar[i].z);
            ap[3] = f2tf32(ar[i].w);
            int kk = idx >> 5, col = (idx & 31) * 4;
            uint4 v;
            v.x = f2tf32(br[i].x);
            v.y = f2tf32(br[i].y);
            v.z = f2tf32(br[i].z);
            v.w = f2tf32(br[i].w);
            *reinterpret_cast<uint4*>(&Bs[buf][kk * BST + col]) = v;
        }
    };

    float acc[2][8][4];
#pragma unroll
    for (int f = 0; f < 2; f++)
#pragma unroll
        for (int nf = 0; nf < 8; nf++)
#pragma unroll
            for (int j = 0; j < 4; j++) acc[f][nf][j] = 0.f;

    auto compute = [&](int buf) {
#pragma unroll
        for (int kk = 0; kk < BK; kk += 8) {
            uint32_t breg[8][2];
#pragma unroll
            for (int nf = 0; nf < 8; nf++) {
                breg[nf][0] = Bs[buf][(kk + t) * BST + wn + nf * 8 + g];
                breg[nf][1] = Bs[buf][(kk + t + 4) * BST + wn + nf * 8 + g];
            }
            uint32_t areg[2][4];
#pragma unroll
            for (int f = 0; f < 2; f++) {
                int r0 = wm + f * 16 + g;
                areg[f][0] = As[buf][r0 * AST + kk + t];
                areg[f][1] = As[buf][(r0 + 8) * AST + kk + t];
                areg[f][2] = As[buf][r0 * AST + kk + t + 4];
                areg[f][3] = As[buf][(r0 + 8) * AST + kk + t + 4];
            }
#pragma unroll
            for (int f = 0; f < 2; f++)
#pragma unroll
                for (int nf = 0; nf < 8; nf++)
                    mma_tf32(acc[f][nf], areg[f], breg[nf]);
        }
    };

    const int NC = NPARTS * 8;
    load_tile(0);
    store_tile(0);
    __syncthreads();
    for (int c = 0; c < NC; c++) {
        if (c + 1 < NC) load_tile(c + 1);
        compute(c & 1);
        __syncthreads();
        if (c + 1 < NC) {
            store_tile((c + 1) & 1);
            __syncthreads();
        }
    }

    // Epilogue
    float* Cbase = C + (size_t)bz * sC + (size_t)(mtile * BM) * HW + ntile * BN;
#pragma unroll
    for (int f = 0; f < 2; f++) {
#pragma unroll
        for (int nf = 0; nf < 8; nf++) {
            int row = wm + f * 16 + g;
            int col = wn + nf * 8 + t * 2;
            *reinterpret_cast<float2*>(Cbase + (size_t)row * HW + col) =
                make_float2(acc[f][nf][0], acc[f][nf][1]);
            *reinterpret_cast<float2*>(Cbase + (size_t)(row + 8) * HW + col) =
                make_float2(acc[f][nf][2], acc[f][nf][3]);
        }
    }
}

// ---------------------------------------------------------------------------
// 6) Fused softmax(k rows) + content lambda (scaled)
//    One block per (b, nh): reads k,v once. Warp w handles k-rows 2w, 2w+1.
// ---------------------------------------------------------------------------
__global__ __launch_bounds__(256) void k_softmax_lambda(const float* __restrict__ qkv,
                                                        float* __restrict__ lambda) {
    const int bh = blockIdx.x;  // 0..127
    const int b = bh >> 3, nh = bh & 7;
    const float* kbase = qkv + ((size_t)b * 384 + 128 + nh * 16) * HW;
    const float* vbase = qkv + ((size_t)b * 384 + 256 + nh * 16) * HW;
    const int warp = threadIdx.x >> 5, lane = threadIdx.x & 31;
    const int i0 = warp * 2;
    const float* k0 = kbase + (size_t)i0 * HW;
    const float* k1 = kbase + (size_t)(i0 + 1) * HW;

    // pass 1: row maxes
    float mx0 = -1e30f, mx1 = -1e30f;
    for (int n = lane; n < HW; n += 32) {
        mx0 = fmaxf(mx0, k0[n]);
        mx1 = fmaxf(mx1, k1[n]);
    }
#pragma unroll
    for (int off = 16; off > 0; off >>= 1) {
        mx0 = fmaxf(mx0, __shfl_xor_sync(0xffffffff, mx0, off));
        mx1 = fmaxf(mx1, __shfl_xor_sync(0xffffffff, mx1, off));
    }

    // pass 2: sumexp + dot with all 16 v rows
    float acc[2][16];
#pragma unroll
    for (int r = 0; r < 2; r++)
#pragma unroll
        for (int o = 0; o < 16; o++) acc[r][o] = 0.f;
    float se0 = 0.f, se1 = 0.f;

    for (int n = lane; n < HW; n += 32) {
        float e0 = __expf(k0[n] - mx0);
        float e1 = __expf(k1[n] - mx1);
        se0 += e0;
        se1 += e1;
#pragma unroll
        for (int o = 0; o < 16; o++) {
            float v = vbase[(size_t)o * HW + n];
            acc[0][o] += e0 * v;
            acc[1][o] += e1 * v;
        }
    }

#pragma unroll
    for (int off = 16; off > 0; off >>= 1) {
        se0 += __shfl_xor_sync(0xffffffff, se0, off);
        se1 += __shfl_xor_sync(0xffffffff, se1, off);
#pragma unroll
        for (int r = 0; r < 2; r++)
#pragma unroll
            for (int o = 0; o < 16; o++)
                acc[r][o] += __shfl_xor_sync(0xffffffff, acc[r][o], off);
    }

    if (lane == 0) {
        float inv0 = 0.25f / se0;  // 0.25 = HD^-0.5
        float inv1 = 0.25f / se1;
        float* lp = lambda + (size_t)bh * 256;
#pragma unroll
        for (int o = 0; o < 16; o++) {
            lp[(i0 + 0) * 16 + o] = acc[0][o] * inv0;
            lp[(i0 + 1) * 16 + o] = acc[1][o] * inv1;
        }
    }
}

// ---------------------------------------------------------------------------
// 7) result1 = content_output + q * position_lambda
// ---------------------------------------------------------------------------
__global__ __launch_bounds__(256) void k_result1(const float* __restrict__ qkv,
                                                 const float* __restrict__ lambda,
                                                 const float* __restrict__ rel_pos,
                                                 float* __restrict__ r1) {
    const int bh = blockIdx.z;  // 0..127
    const int b = bh >> 3, nh = bh & 7;
    const int x0 = blockIdx.x * 16, y0 = blockIdx.y * 16;
    const int tid = threadIdx.x;
    const int px = tid & 15, py = tid >> 4;

    __shared__ float lam[16][16];        // [i][o]
    __shared__ float relw[16][25];
    __shared__ float qs[16][16][16];     // [ch][y][x]
    __shared__ float vs[16][20][20];     // [ch][y][x] with 2-halo

    lam[py][px] = lambda[((size_t)bh * 16 + py) * 16 + px];
    for (int t = tid; t < 400; t += 256) relw[t / 25][t % 25] = rel_pos[t];
    const float* qbase = qkv + ((size_t)b * 384 + nh * 16) * HW;
#pragma unroll
    for (int ch = 0; ch < 16; ch++) {
        qs[ch][py][px] = qbase[(size_t)ch * HW + (y0 + py) * Ww + x0 + px];
    }
    const float* vbase = qkv + ((size_t)b * 384 + 256 + nh * 16) * HW;
    for (int t = tid; t < 6400; t += 256) {
        int ch = t / 400;
        int r = t % 400;
        int vy = r / 20, vx = r % 20;
        int gy = y0 + vy - 2, gx = x0 + vx - 2;
        float val = 0.f;
        if (gy >= 0 && gy < Hh && gx >= 0 && gx < Ww)
            val = vbase[(size_t)ch * HW + gy * Ww + gx];
        vs[ch][vy][vx] = val;
    }
    __syncthreads();

    float* obase = r1 + ((size_t)b * Cc + nh * 16) * HW + (y0 + py) * Ww + x0 + px;
#pragma unroll
    for (int o = 0; o < 16; o++) {
        float content = 0.f;
#pragma unroll
        for (int i = 0; i < 16; i++) content += qs[i][py][px] * lam[i][o];
        float pos = 0.f;
#pragma unroll
        for (int ky = 0; ky < 5; ky++)
#pragma unroll
            for (int kx = 0; kx < 5; kx++)
                pos += relw[o][ky * 5 + kx] * vs[o][py + ky][px + kx];
        obase[(size_t)o * HW] = content + qs[o][py][px] * pos;
    }
}

// ---------------------------------------------------------------------------
// Launch
// ---------------------------------------------------------------------------
extern "C" void kernel_launch(void* const* d_in, const int* in_sizes, int n_in,
                              void* d_out, int out_size) {
    const float* src      = (const float*)d_in[0];
    const float* cpe_w    = (const float*)d_in[1];
    const float* qkv_w    = (const float*)d_in[2];
    const float* rel_pos  = (const float*)d_in[3];
    const float* conv1d_w = (const float*)d_in[4];
    const float* out_w    = (const float*)d_in[5];
    float* out = (float*)d_out;

    float *s_p, *qkv_p, *lam_p, *pool_p, *ca_p, *w2b_p, *r1_p;
    cudaGetSymbolAddress((void**)&s_p,    g_s);
    cudaGetSymbolAddress((void**)&qkv_p,  g_qkv);
    cudaGetSymbolAddress((void**)&lam_p,  g_lambda);
    cudaGetSymbolAddress((void**)&pool_p, g_pool);
    cudaGetSymbolAddress((void**)&ca_p,   g_ca);
    cudaGetSymbolAddress((void**)&w2b_p,  g_w2b);
    cudaGetSymbolAddress((void**)&r1_p,   g_r1);

    // 1) CPE
    k_cpe<<<(Bb * Cc * HW + 255) / 256, 256>>>(src, cpe_w, s_p);
    // 2) Pool + ECA + w2b
    k_pool<<<Bb * Cc, 256>>>(src, pool_p);
    k_eca<<<(Bb * Cc + 255) / 256, 256>>>(pool_p, conv1d_w, ca_p);
    k_w2b<<<(Bb * OUTC * Cc + 255) / 256, 256>>>(out_w, ca_p, w2b_p);
    // 3) QKV GEMM (tf32 MMA): per batch (384x128)@(128x4096)
    {
        dim3 grid(HW / 128, 3 * Cc / 128, Bb);
        k_mma_gemm<1><<<grid, 256>>>(qkv_w, 0, Cc,
                                     s_p, (size_t)Cc * HW,
                                     nullptr, 0, 0, nullptr, 0,
                                     qkv_p, (size_t)3 * Cc * HW);
    }
    // 4) softmax + lambda
    k_softmax_lambda<<<Bb * NHh, 256>>>(qkv_p, lam_p);
    // 5) result1
    {
        dim3 grid(Ww / 16, Hh / 16, Bb * NHh);
        k_result1<<<grid, 256>>>(qkv_p, lam_p, rel_pos, r1_p);
    }
    // 6) output GEMM (tf32 MMA): out = out_w[:, :128] @ r1 + w2b @ src
    {
        dim3 grid(HW / 128, OUTC / 128, Bb);
        k_mma_gemm<2><<<grid, 256>>>(out_w, 0, 2 * Cc,
                                     r1_p, (size_t)Cc * HW,
                                     w2b_p, (size_t)OUTC * Cc, Cc,
                                     src, (size_t)Cc * HW,
                                     out, (size_t)OUTC * HW);
    }
}

// round 3
// speedup vs baseline: 1.8963x; 1.5635x over previous
#include <cuda_runtime.h>
#include <cstdint>
#include <cstddef>

#define Bb   16
#define Cc   128
#define Hh   64
#define Ww   64
#define NHh  8
#define HDd  16
#define HW   4096
#define OUTC 512

// ---------------------------------------------------------------------------
// Scratch
// ---------------------------------------------------------------------------
__device__ float g_s[Bb * Cc * HW];
__device__ float g_qkv[Bb * 3 * Cc * HW];
__device__ float g_lambda[Bb * NHh * HDd * HDd];
__device__ float g_pool[Bb * Cc];
__device__ float g_w2b[Bb * OUTC * Cc];
__device__ float g_r1[Bb * Cc * HW];

// ---------------------------------------------------------------------------
// helpers
// ---------------------------------------------------------------------------
__device__ __forceinline__ uint32_t f2tf32(float x) {
    uint32_t r;
    asm("cvt.rna.tf32.f32 %0, %1;" : "=r"(r) : "f"(x));
    return r;
}

__device__ __forceinline__ void mma_tf32(float* c, const uint32_t* a, const uint32_t* b) {
    asm volatile(
        "mma.sync.aligned.m16n8k8.row.col.f32.tf32.tf32.f32 "
        "{%0,%1,%2,%3}, {%4,%5,%6,%7}, {%8,%9}, {%0,%1,%2,%3};\n"
        : "+f"(c[0]), "+f"(c[1]), "+f"(c[2]), "+f"(c[3])
        : "r"(a[0]), "r"(a[1]), "r"(a[2]), "r"(a[3]), "r"(b[0]), "r"(b[1]));
}

__device__ __forceinline__ void cp16(uint32_t smem, const void* gptr) {
    asm volatile("cp.async.cg.shared.global [%0], [%1], 16;\n" :: "r"(smem), "l"(gptr));
}
__device__ __forceinline__ void cp_commit() {
    asm volatile("cp.async.commit_group;\n");
}
template <int N>
__device__ __forceinline__ void cp_wait() {
    asm volatile("cp.async.wait_group %0;\n" :: "n"(N));
}

// ---------------------------------------------------------------------------
// 1) CPE: s = dwconv3x3(src, cpe_w) + src   (4 pixels / thread, float4)
// ---------------------------------------------------------------------------
__global__ __launch_bounds__(256) void k_cpe(const float* __restrict__ src,
                                             const float* __restrict__ cpe_w,
                                             float* __restrict__ s) {
    int gid = blockIdx.x * 256 + threadIdx.x;       // 0 .. 2M-1
    int p4 = gid * 4;
    int x = p4 & 63;              // 0,4,...,60
    int h = (p4 >> 6) & 63;
    int c = (p4 >> 12) & 127;
    const float* wp = cpe_w + c * 9;

    float a0 = 0.f, a1 = 0.f, a2 = 0.f, a3 = 0.f;
    float4 ctr = *reinterpret_cast<const float4*>(src + p4);

#pragma unroll
    for (int dy = -1; dy <= 1; dy++) {
        int hy = h + dy;
        if (hy < 0 || hy >= Hh) continue;
        const float* r = src + p4 + dy * Ww;
        float4 m = (dy == 0) ? ctr : *reinterpret_cast<const float4*>(r);
        float lft = (x > 0)  ? r[-1] : 0.f;
        float rgt = (x < 60) ? r[4]  : 0.f;
        float wl = wp[(dy + 1) * 3 + 0];
        float wc = wp[(dy + 1) * 3 + 1];
        float wr = wp[(dy + 1) * 3 + 2];
        a0 += wl * lft + wc * m.x + wr * m.y;
        a1 += wl * m.x + wc * m.y + wr * m.z;
        a2 += wl * m.y + wc * m.z + wr * m.w;
        a3 += wl * m.z + wc * m.w + wr * rgt;
    }
    float4 o = make_float4(a0 + ctr.x, a1 + ctr.y, a2 + ctr.z, a3 + ctr.w);
    *reinterpret_cast<float4*>(s + p4) = o;
}

// ---------------------------------------------------------------------------
// 2) Pool
// ---------------------------------------------------------------------------
__global__ __launch_bounds__(256) void k_pool(const float* __restrict__ src,
                                              float* __restrict__ pool) {
    int bc = blockIdx.x;
    const float* p = src + (size_t)bc * HW;
    float sum = 0.f;
    for (int n = threadIdx.x; n < HW; n += 256) sum += p[n];
    __shared__ float sm[256];
    sm[threadIdx.x] = sum;
    __syncthreads();
    for (int sstep = 128; sstep > 0; sstep >>= 1) {
        if (threadIdx.x < sstep) sm[threadIdx.x] += sm[threadIdx.x + sstep];
        __syncthreads();
    }
    if (threadIdx.x == 0) pool[bc] = sm[0] * (1.0f / HW);
}

// ---------------------------------------------------------------------------
// 3) fused ECA + w2b: w2b[b][o][c] = out_w[o][128+c] * sigmoid(conv1d(pool)[b][c])
// ---------------------------------------------------------------------------
__global__ __launch_bounds__(256) void k_w2b(const float* __restrict__ out_w,
                                             const float* __restrict__ pool,
                                             const float* __restrict__ conv1d_w,
                                             float* __restrict__ w2b) {
    int idx = blockIdx.x * 256 + threadIdx.x;
    if (idx >= Bb * OUTC * Cc) return;
    int c = idx & 127;
    int o = (idx >> 7) & 511;
    int b = idx >> 16;
    int pc = (b << 7) + c;
    float left  = (c > 0)   ? pool[pc - 1] : 0.f;
    float mid   = pool[pc];
    float right = (c < 127) ? pool[pc + 1] : 0.f;
    float z = conv1d_w[0] * left + conv1d_w[1] * mid + conv1d_w[2] * right;
    float ca = 1.0f / (1.0f + __expf(-z));
    w2b[idx] = out_w[o * 256 + 128 + c] * ca;
}

// ---------------------------------------------------------------------------
// 4) tf32 GEMM, cp.async pipelined. 128 threads = 4 warps, warp tile 64x64.
//    C[b] = sum_p A_p[b] (M x 128, lda_p) @ B_p[b] (128 x 4096)
// ---------------------------------------------------------------------------
template <int NPARTS>
__global__ __launch_bounds__(128) void k_mma_gemm(
    const float* __restrict__ A0, size_t sA0, int lda0,
    const float* __restrict__ B0, size_t sB0,
    const float* __restrict__ A1, size_t sA1, int lda1,
    const float* __restrict__ B1, size_t sB1,
    float* __restrict__ C, size_t sC) {
    constexpr int BM = 128, BN = 128, BK = 16;
    constexpr int AST = 20;    // As row stride (words): frag-load conflict-free
    constexpr int BST = 136;   // Bs row stride (words): frag-load conflict-free

    __shared__ float As[2][BM * AST];
    __shared__ float Bs[2][BK * BST];

    const int tid = threadIdx.x;
    const int bz = blockIdx.z, mtile = blockIdx.y, ntile = blockIdx.x;
    const int warp = tid >> 5, lane = tid & 31;
    const int g = lane >> 2, t = lane & 3;
    const int wm = (warp >> 1) * 64, wn = (warp & 1) * 64;

    auto load_chunk = [&](int c, int buf) {
        const int part = (NPARTS == 2) ? (c >> 3) : 0;
        const int kin = (c & 7) * BK;
        const float* A = part ? A1 + (size_t)bz * sA1 : A0 + (size_t)bz * sA0;
        const int lda  = part ? lda1 : lda0;
        const float* B = part ? B1 + (size_t)bz * sB1 : B0 + (size_t)bz * sB0;

        // A: each thread owns one m-row, 4 x 16B along k
        uint32_t abase = (uint32_t)__cvta_generic_to_shared(&As[buf][tid * AST]);
        const float* ag = A + (size_t)(mtile * BM + tid) * lda + kin;
#pragma unroll
        for (int q = 0; q < 4; q++) cp16(abase + q * 16, ag + q * 4);

        // B: 512 float4, coalesced
#pragma unroll
        for (int it = 0; it < 4; it++) {
            int idx = tid + it * 128;
            int kk = idx >> 5, col = (idx & 31) * 4;
            uint32_t bdst = (uint32_t)__cvta_generic_to_shared(&Bs[buf][kk * BST + col]);
            cp16(bdst, B + (size_t)(kin + kk) * HW + ntile * BN + col);
        }
        cp_commit();
    };

    float acc[4][8][4];
#pragma unroll
    for (int f = 0; f < 4; f++)
#pragma unroll
        for (int nf = 0; nf < 8; nf++)
#pragma unroll
            for (int j = 0; j < 4; j++) acc[f][nf][j] = 0.f;

    auto compute = [&](int buf) {
#pragma unroll
        for (int kk = 0; kk < BK; kk += 8) {
            uint32_t breg[8][2];
#pragma unroll
            for (int nf = 0; nf < 8; nf++) {
                breg[nf][0] = f2tf32(Bs[buf][(kk + t) * BST + wn + nf * 8 + g]);
                breg[nf][1] = f2tf32(Bs[buf][(kk + t + 4) * BST + wn + nf * 8 + g]);
            }
            uint32_t areg[4][4];
#pragma unroll
            for (int f = 0; f < 4; f++) {
                int r0 = wm + f * 16 + g;
                areg[f][0] = f2tf32(As[buf][r0 * AST + kk + t]);
                areg[f][1] = f2tf32(As[buf][(r0 + 8) * AST + kk + t]);
                areg[f][2] = f2tf32(As[buf][r0 * AST + kk + t + 4]);
                areg[f][3] = f2tf32(As[buf][(r0 + 8) * AST + kk + t + 4]);
            }
#pragma unroll
            for (int f = 0; f < 4; f++)
#pragma unroll
                for (int nf = 0; nf < 8; nf++)
                    mma_tf32(acc[f][nf], areg[f], breg[nf]);
        }
    };

    const int NC = NPARTS * 8;
    load_chunk(0, 0);
    for (int c = 0; c < NC; c++) {
        if (c + 1 < NC) {
            load_chunk(c + 1, (c + 1) & 1);
            cp_wait<1>();
        } else {
            cp_wait<0>();
        }
        __syncthreads();
        compute(c & 1);
        __syncthreads();
    }

    float* Cbase = C + (size_t)bz * sC + (size_t)(mtile * BM) * HW + ntile * BN;
#pragma unroll
    for (int f = 0; f < 4; f++) {
#pragma unroll
        for (int nf = 0; nf < 8; nf++) {
            int row = wm + f * 16 + g;
            int col = wn + nf * 8 + t * 2;
            *reinterpret_cast<float2*>(Cbase + (size_t)row * HW + col) =
                make_float2(acc[f][nf][0], acc[f][nf][1]);
            *reinterpret_cast<float2*>(Cbase + (size_t)(row + 8) * HW + col) =
                make_float2(acc[f][nf][2], acc[f][nf][3]);
        }
    }
}

// ---------------------------------------------------------------------------
// 5) softmax + lambda. grid (128, 2): block = (bh, half of 8 k-rows).
//    v staged through smem in 512-wide chunks (read once per block).
// ---------------------------------------------------------------------------
__global__ __launch_bounds__(256) void k_softmax_lambda(const float* __restrict__ qkv,
                                                        float* __restrict__ lambda) {
    const int bh = blockIdx.x;
    const int half = blockIdx.y;
    const int b = bh >> 3, nh = bh & 7;
    const float* kbase = qkv + ((size_t)b * 384 + 128 + nh * 16) * HW;
    const float* vbase = qkv + ((size_t)b * 384 + 256 + nh * 16) * HW;
    const int tid = threadIdx.x;
    const int warp = tid >> 5, lane = tid & 31;
    const int i = half * 8 + warp;
    const float* krow = kbase + (size_t)i * HW;

    __shared__ float vsm[16][512];   // 32 KB

    // row max
    float mx = -1e30f;
    for (int n = lane; n < HW; n += 32) mx = fmaxf(mx, krow[n]);
#pragma unroll
    for (int off = 16; off > 0; off >>= 1)
        mx = fmaxf(mx, __shfl_xor_sync(0xffffffff, mx, off));

    float acc[16];
#pragma unroll
    for (int o = 0; o < 16; o++) acc[o] = 0.f;
    float se = 0.f;

    for (int n0 = 0; n0 < HW; n0 += 512) {
        __syncthreads();
        for (int t2 = tid; t2 < 16 * 512; t2 += 256) {
            int o = t2 >> 9, n = t2 & 511;
            vsm[o][n] = vbase[(size_t)o * HW + n0 + n];
        }
        __syncthreads();
#pragma unroll 4
        for (int n = lane; n < 512; n += 32) {
            float e = __expf(krow[n0 + n] - mx);
            se += e;
#pragma unroll
            for (int o = 0; o < 16; o++) acc[o] += e * vsm[o][n];
        }
    }

#pragma unroll
    for (int off = 16; off > 0; off >>= 1) {
        se += __shfl_xor_sync(0xffffffff, se, off);
#pragma unroll
        for (int o = 0; o < 16; o++)
            acc[o] += __shfl_xor_sync(0xffffffff, acc[o], off);
    }
    if (lane == 0) {
        float inv = 0.25f / se;   // 0.25 = HD^-0.5
        float* lp = lambda + (size_t)bh * 256 + i * 16;
#pragma unroll
        for (int o = 0; o < 16; o++) lp[o] = acc[o] * inv;
    }
}

// ---------------------------------------------------------------------------
// 6) result1 = content + q * position_lambda
// ---------------------------------------------------------------------------
__global__ __launch_bounds__(256) void k_result1(const float* __restrict__ qkv,
                                                 const float* __restrict__ lambda,
                                                 const float* __restrict__ rel_pos,
                                                 float* __restrict__ r1) {
    const int bh = blockIdx.z;
    const int b = bh >> 3, nh = bh & 7;
    const int x0 = blockIdx.x * 16, y0 = blockIdx.y * 16;
    const int tid = threadIdx.x;
    const int px = tid & 15, py = tid >> 4;

    __shared__ float lam[16][16];
    __shared__ float relw[16][25];
    __shared__ float qs[16][16][16];
    __shared__ float vs[16][20][20];

    lam[py][px] = lambda[((size_t)bh * 16 + py) * 16 + px];
    for (int t = tid; t < 400; t += 256) relw[t / 25][t % 25] = rel_pos[t];
    const float* qbase = qkv + ((size_t)b * 384 + nh * 16) * HW;
#pragma unroll
    for (int ch = 0; ch < 16; ch++)
        qs[ch][py][px] = qbase[(size_t)ch * HW + (y0 + py) * Ww + x0 + px];
    const float* vbase = qkv + ((size_t)b * 384 + 256 + nh * 16) * HW;
    for (int t = tid; t < 6400; t += 256) {
        int ch = t / 400;
        int r = t % 400;
        int vy = r / 20, vx = r % 20;
        int gy = y0 + vy - 2, gx = x0 + vx - 2;
        float val = 0.f;
        if (gy >= 0 && gy < Hh && gx >= 0 && gx < Ww)
            val = vbase[(size_t)ch * HW + gy * Ww + gx];
        vs[ch][vy][vx] = val;
    }
    __syncthreads();

    float* obase = r1 + ((size_t)b * Cc + nh * 16) * HW + (y0 + py) * Ww + x0 + px;
#pragma unroll
    for (int o = 0; o < 16; o++) {
        float content = 0.f;
#pragma unroll
        for (int i = 0; i < 16; i++) content += qs[i][py][px] * lam[i][o];
        float pos = 0.f;
#pragma unroll
        for (int ky = 0; ky < 5; ky++)
#pragma unroll
            for (int kx = 0; kx < 5; kx++)
                pos += relw[o][ky * 5 + kx] * vs[o][py + ky][px + kx];
        obase[(size_t)o * HW] = content + qs[o][py][px] * pos;
    }
}

// ---------------------------------------------------------------------------
// Launch
// ---------------------------------------------------------------------------
extern "C" void kernel_launch(void* const* d_in, const int* in_sizes, int n_in,
                              void* d_out, int out_size) {
    const float* src      = (const float*)d_in[0];
    const float* cpe_w    = (const float*)d_in[1];
    const float* qkv_w    = (const float*)d_in[2];
    const float* rel_pos  = (const float*)d_in[3];
    const float* conv1d_w = (const float*)d_in[4];
    const float* out_w    = (const float*)d_in[5];
    float* out = (float*)d_out;

    float *s_p, *qkv_p, *lam_p, *pool_p, *w2b_p, *r1_p;
    cudaGetSymbolAddress((void**)&s_p,    g_s);
    cudaGetSymbolAddress((void**)&qkv_p,  g_qkv);
    cudaGetSymbolAddress((void**)&lam_p,  g_lambda);
    cudaGetSymbolAddress((void**)&pool_p, g_pool);
    cudaGetSymbolAddress((void**)&w2b_p,  g_w2b);
    cudaGetSymbolAddress((void**)&r1_p,   g_r1);

    k_cpe<<<Bb * Cc * HW / 1024, 256>>>(src, cpe_w, s_p);
    k_pool<<<Bb * Cc, 256>>>(src, pool_p);
    k_w2b<<<(Bb * OUTC * Cc + 255) / 256, 256>>>(out_w, pool_p, conv1d_w, w2b_p);
    {
        dim3 grid(HW / 128, 3 * Cc / 128, Bb);
        k_mma_gemm<1><<<grid, 128>>>(qkv_w, 0, Cc,
                                     s_p, (size_t)Cc * HW,
                                     nullptr, 0, 0, nullptr, 0,
                                     qkv_p, (size_t)3 * Cc * HW);
    }
    {
        dim3 grid(Bb * NHh, 2);
        k_softmax_lambda<<<grid, 256>>>(qkv_p, lam_p);
    }
    {
        dim3 grid(Ww / 16, Hh / 16, Bb * NHh);
        k_result1<<<grid, 256>>>(qkv_p, lam_p, rel_pos, r1_p);
    }
    {
        dim3 grid(HW / 128, OUTC / 128, Bb);
        k_mma_gemm<2><<<grid, 128>>>(out_w, 0, 2 * Cc,
                                     r1_p, (size_t)Cc * HW,
                                     w2b_p, (size_t)OUTC * Cc, Cc,
                                     src, (size_t)Cc * HW,
                                     out, (size_t)OUTC * HW);
    }
}

// round 5
// speedup vs baseline: 1.9053x; 1.0047x over previous
#include <cuda_runtime.h>
#include <cstdint>
#include <cstddef>

#define Bb   16
#define Cc   128
#define Hh   64
#define Ww   64
#define NHh  8
#define HDd  16
#define HW   4096
#define OUTC 512

// ---------------------------------------------------------------------------
// Scratch
// ---------------------------------------------------------------------------
__device__ float g_s[Bb * Cc * HW];
__device__ float g_qkv[Bb * 3 * Cc * HW];
__device__ float g_lambda[Bb * NHh * HDd * HDd];
__device__ float g_pool[Bb * Cc];
__device__ float g_w2b[Bb * OUTC * Cc];
__device__ float g_r1[Bb * Cc * HW];

// ---------------------------------------------------------------------------
// helpers
// ---------------------------------------------------------------------------
__device__ __forceinline__ uint32_t f2tf32(float x) {
    uint32_t r;
    asm("cvt.rna.tf32.f32 %0, %1;" : "=r"(r) : "f"(x));
    return r;
}

__device__ __forceinline__ void mma_tf32(float* c, const uint32_t* a, const uint32_t* b) {
    asm volatile(
        "mma.sync.aligned.m16n8k8.row.col.f32.tf32.tf32.f32 "
        "{%0,%1,%2,%3}, {%4,%5,%6,%7}, {%8,%9}, {%0,%1,%2,%3};\n"
        : "+f"(c[0]), "+f"(c[1]), "+f"(c[2]), "+f"(c[3])
        : "r"(a[0]), "r"(a[1]), "r"(a[2]), "r"(a[3]), "r"(b[0]), "r"(b[1]));
}

__device__ __forceinline__ void cp16(uint32_t smem, const void* gptr) {
    asm volatile("cp.async.cg.shared.global [%0], [%1], 16;\n" :: "r"(smem), "l"(gptr));
}
__device__ __forceinline__ void cp_commit() {
    asm volatile("cp.async.commit_group;\n");
}
template <int N>
__device__ __forceinline__ void cp_wait() {
    asm volatile("cp.async.wait_group %0;\n" :: "n"(N));
}

// ---------------------------------------------------------------------------
// 1) CPE: s = dwconv3x3(src, cpe_w) + src   (4 pixels / thread, float4)
// ---------------------------------------------------------------------------
__global__ __launch_bounds__(256) void k_cpe(const float* __restrict__ src,
                                             const float* __restrict__ cpe_w,
                                             float* __restrict__ s) {
    int gid = blockIdx.x * 256 + threadIdx.x;
    int p4 = gid * 4;
    int x = p4 & 63;
    int h = (p4 >> 6) & 63;
    int c = (p4 >> 12) & 127;
    const float* wp = cpe_w + c * 9;

    float a0 = 0.f, a1 = 0.f, a2 = 0.f, a3 = 0.f;
    float4 ctr = *reinterpret_cast<const float4*>(src + p4);

#pragma unroll
    for (int dy = -1; dy <= 1; dy++) {
        int hy = h + dy;
        if (hy < 0 || hy >= Hh) continue;
        const float* r = src + p4 + dy * Ww;
        float4 m = (dy == 0) ? ctr : *reinterpret_cast<const float4*>(r);
        float lft = (x > 0)  ? r[-1] : 0.f;
        float rgt = (x < 60) ? r[4]  : 0.f;
        float wl = wp[(dy + 1) * 3 + 0];
        float wc = wp[(dy + 1) * 3 + 1];
        float wr = wp[(dy + 1) * 3 + 2];
        a0 += wl * lft + wc * m.x + wr * m.y;
        a1 += wl * m.x + wc * m.y + wr * m.z;
        a2 += wl * m.y + wc * m.z + wr * m.w;
        a3 += wl * m.z + wc * m.w + wr * rgt;
    }
    float4 o = make_float4(a0 + ctr.x, a1 + ctr.y, a2 + ctr.z, a3 + ctr.w);
    *reinterpret_cast<float4*>(s + p4) = o;
}

// ---------------------------------------------------------------------------
// 2) Pool
// ---------------------------------------------------------------------------
__global__ __launch_bounds__(256) void k_pool(const float* __restrict__ src,
                                              float* __restrict__ pool) {
    int bc = blockIdx.x;
    const float* p = src + (size_t)bc * HW;
    float sum = 0.f;
    for (int n = threadIdx.x; n < HW; n += 256) sum += p[n];
    __shared__ float sm[256];
    sm[threadIdx.x] = sum;
    __syncthreads();
    for (int sstep = 128; sstep > 0; sstep >>= 1) {
        if (threadIdx.x < sstep) sm[threadIdx.x] += sm[threadIdx.x + sstep];
        __syncthreads();
    }
    if (threadIdx.x == 0) pool[bc] = sm[0] * (1.0f / HW);
}

// ---------------------------------------------------------------------------
// 3) fused ECA + w2b
// ---------------------------------------------------------------------------
__global__ __launch_bounds__(256) void k_w2b(const float* __restrict__ out_w,
                                             const float* __restrict__ pool,
                                             const float* __restrict__ conv1d_w,
                                             float* __restrict__ w2b) {
    int idx = blockIdx.x * 256 + threadIdx.x;
    if (idx >= Bb * OUTC * Cc) return;
    int c = idx & 127;
    int o = (idx >> 7) & 511;
    int b = idx >> 16;
    int pc = (b << 7) + c;
    float left  = (c > 0)   ? pool[pc - 1] : 0.f;
    float mid   = pool[pc];
    float right = (c < 127) ? pool[pc + 1] : 0.f;
    float z = conv1d_w[0] * left + conv1d_w[1] * mid + conv1d_w[2] * right;
    float ca = 1.0f / (1.0f + __expf(-z));
    w2b[idx] = out_w[o * 256 + 128 + c] * ca;
}

// ---------------------------------------------------------------------------
// 4) tf32 GEMM: 256 threads / 8 warps, warp tile 64x32, 3-stage cp.async,
//    one __syncthreads per K-chunk. grid: (mtile, ntile, batch).
//    C[b] = sum_p A_p[b] (M x 128, lda_p) @ B_p[b] (128 x 4096)
// ---------------------------------------------------------------------------
template <int NPARTS>
__global__ __launch_bounds__(256) void k_mma_gemm(
    const float* __restrict__ A0, size_t sA0, int lda0,
    const float* __restrict__ B0, size_t sB0,
    const float* __restrict__ A1, size_t sA1, int lda1,
    const float* __restrict__ B1, size_t sB1,
    float* __restrict__ C, size_t sC) {
    constexpr int BlkM = 128, BlkN = 128, BlkK = 16;
    constexpr int AST = 20;    // As row stride (words), conflict-free frag loads
    constexpr int BST = 136;   // Bs row stride (words), conflict-free frag loads
    constexpr int ASZ = BlkM * AST;  // 2560
    constexpr int BSZ = BlkK * BST;  // 2176

    extern __shared__ float smbuf[];
    float* Asm = smbuf;              // 3 buffers
    float* Bsm = smbuf + 3 * ASZ;    // 3 buffers

    const int tid = threadIdx.x;
    const int bz = blockIdx.z, mtile = blockIdx.x, ntile = blockIdx.y;
    const int warp = tid >> 5, lane = tid & 31;
    const int g = lane >> 2, t = lane & 3;
    const int wm = (warp >> 2) * 64;    // 2 warp-rows of 64
    const int wn = (warp & 3) * 32;     // 4 warp-cols of 32

    auto load_chunk = [&](int cidx, int buf) {
        const int part = (NPARTS == 2) ? (cidx >> 3) : 0;
        const int kin = (cidx & 7) * BlkK;
        const float* Aptr = part ? A1 + (size_t)bz * sA1 : A0 + (size_t)bz * sA0;
        const int lda  = part ? lda1 : lda0;
        const float* Bptr = part ? B1 + (size_t)bz * sB1 : B0 + (size_t)bz * sB0;
        float* Abuf = Asm + buf * ASZ;
        float* Bbuf = Bsm + buf * BSZ;
#pragma unroll
        for (int i = 0; i < 2; i++) {
            int idx = tid + i * 256;
            int row = idx >> 2, kq = (idx & 3) * 4;
            cp16((uint32_t)__cvta_generic_to_shared(&Abuf[row * AST + kq]),
                 Aptr + (size_t)(mtile * BlkM + row) * lda + kin + kq);
            int kk = idx >> 5, col = (idx & 31) * 4;
            cp16((uint32_t)__cvta_generic_to_shared(&Bbuf[kk * BST + col]),
                 Bptr + (size_t)(kin + kk) * HW + ntile * BlkN + col);
        }
        cp_commit();
    };

    float acc[4][4][4];
#pragma unroll
    for (int f = 0; f < 4; f++)
#pragma unroll
        for (int nf = 0; nf < 4; nf++)
#pragma unroll
            for (int j = 0; j < 4; j++) acc[f][nf][j] = 0.f;

    auto compute = [&](int buf) {
        const float* Abuf = Asm + buf * ASZ;
        const float* Bbuf = Bsm + buf * BSZ;
#pragma unroll
        for (int kk = 0; kk < BlkK; kk += 8) {
            uint32_t breg[4][2];
#pragma unroll
            for (int nf = 0; nf < 4; nf++) {
                breg[nf][0] = f2tf32(Bbuf[(kk + t) * BST + wn + nf * 8 + g]);
                breg[nf][1] = f2tf32(Bbuf[(kk + t + 4) * BST + wn + nf * 8 + g]);
            }
            uint32_t areg[4][4];
#pragma unroll
            for (int f = 0; f < 4; f++) {
                int r0 = wm + f * 16 + g;
                areg[f][0] = f2tf32(Abuf[r0 * AST + kk + t]);
                areg[f][1] = f2tf32(Abuf[(r0 + 8) * AST + kk + t]);
                areg[f][2] = f2tf32(Abuf[r0 * AST + kk + t + 4]);
                areg[f][3] = f2tf32(Abuf[(r0 + 8) * AST + kk + t + 4]);
            }
#pragma unroll
            for (int f = 0; f < 4; f++)
#pragma unroll
                for (int nf = 0; nf < 4; nf++)
                    mma_tf32(acc[f][nf], areg[f], breg[nf]);
        }
    };

    const int NC = NPARTS * 8;
    load_chunk(0, 0);
    load_chunk(1, 1);
    for (int cidx = 0; cidx < NC; cidx++) {
        if (cidx < NC - 1) cp_wait<1>(); else cp_wait<0>();
        __syncthreads();
        if (cidx + 2 < NC) load_chunk(cidx + 2, (cidx + 2) % 3);
        compute(cidx % 3);
    }

    float* Cbase = C + (size_t)bz * sC + (size_t)(mtile * BlkM) * HW + ntile * BlkN;
#pragma unroll
    for (int f = 0; f < 4; f++) {
#pragma unroll
        for (int nf = 0; nf < 4; nf++) {
            int row = wm + f * 16 + g;
            int col = wn + nf * 8 + t * 2;
            *reinterpret_cast<float2*>(Cbase + (size_t)row * HW + col) =
                make_float2(acc[f][nf][0], acc[f][nf][1]);
            *reinterpret_cast<float2*>(Cbase + (size_t)(row + 8) * HW + col) =
                make_float2(acc[f][nf][2], acc[f][nf][3]);
        }
    }
}

// ---------------------------------------------------------------------------
// 5) softmax + lambda (v staged through smem)
// ---------------------------------------------------------------------------
__global__ __launch_bounds__(256) void k_softmax_lambda(const float* __restrict__ qkv,
                                                        float* __restrict__ lambda) {
    const int bh = blockIdx.x;
    const int half = blockIdx.y;
    const int b = bh >> 3, nh = bh & 7;
    const float* kbase = qkv + ((size_t)b * 384 + 128 + nh * 16) * HW;
    const float* vbase = qkv + ((size_t)b * 384 + 256 + nh * 16) * HW;
    const int tid = threadIdx.x;
    const int warp = tid >> 5, lane = tid & 31;
    const int i = half * 8 + warp;
    const float* krow = kbase + (size_t)i * HW;

    __shared__ float vsm[16][512];

    float mx = -1e30f;
    for (int n = lane; n < HW; n += 32) mx = fmaxf(mx, krow[n]);
#pragma unroll
    for (int off = 16; off > 0; off >>= 1)
        mx = fmaxf(mx, __shfl_xor_sync(0xffffffff, mx, off));

    float acc[16];
#pragma unroll
    for (int o = 0; o < 16; o++) acc[o] = 0.f;
    float se = 0.f;

    for (int n0 = 0; n0 < HW; n0 += 512) {
        __syncthreads();
        for (int t2 = tid; t2 < 16 * 512; t2 += 256) {
            int o = t2 >> 9, n = t2 & 511;
            vsm[o][n] = vbase[(size_t)o * HW + n0 + n];
        }
        __syncthreads();
#pragma unroll 4
        for (int n = lane; n < 512; n += 32) {
            float e = __expf(krow[n0 + n] - mx);
            se += e;
#pragma unroll
            for (int o = 0; o < 16; o++) acc[o] += e * vsm[o][n];
        }
    }

#pragma unroll
    for (int off = 16; off > 0; off >>= 1) {
        se += __shfl_xor_sync(0xffffffff, se, off);
#pragma unroll
        for (int o = 0; o < 16; o++)
            acc[o] += __shfl_xor_sync(0xffffffff, acc[o], off);
    }
    if (lane == 0) {
        float inv = 0.25f / se;
        float* lp = lambda + (size_t)bh * 256 + i * 16;
#pragma unroll
        for (int o = 0; o < 16; o++) lp[o] = acc[o] * inv;
    }
}

// ---------------------------------------------------------------------------
// 6) result1 = content + q * position_lambda
// ---------------------------------------------------------------------------
__global__ __launch_bounds__(256) void k_result1(const float* __restrict__ qkv,
                                                 const float* __restrict__ lambda,
                                                 const float* __restrict__ rel_pos,
                                                 float* __restrict__ r1) {
    const int bh = blockIdx.z;
    const int b = bh >> 3, nh = bh & 7;
    const int x0 = blockIdx.x * 16, y0 = blockIdx.y * 16;
    const int tid = threadIdx.x;
    const int px = tid & 15, py = tid >> 4;

    __shared__ float lam[16][16];
    __shared__ float relw[16][25];
    __shared__ float qs[16][16][16];
    __shared__ float vs[16][20][20];

    lam[py][px] = lambda[((size_t)bh * 16 + py) * 16 + px];
    for (int t = tid; t < 400; t += 256) relw[t / 25][t % 25] = rel_pos[t];
    const float* qbase = qkv + ((size_t)b * 384 + nh * 16) * HW;
#pragma unroll
    for (int ch = 0; ch < 16; ch++)
        qs[ch][py][px] = qbase[(size_t)ch * HW + (y0 + py) * Ww + x0 + px];
    const float* vbase = qkv + ((size_t)b * 384 + 256 + nh * 16) * HW;
    for (int t = tid; t < 6400; t += 256) {
        int ch = t / 400;
        int r = t % 400;
        int vy = r / 20, vx = r % 20;
        int gy = y0 + vy - 2, gx = x0 + vx - 2;
        float val = 0.f;
        if (gy >= 0 && gy < Hh && gx >= 0 && gx < Ww)
            val = vbase[(size_t)ch * HW + gy * Ww + gx];
        vs[ch][vy][vx] = val;
    }
    __syncthreads();

    float* obase = r1 + ((size_t)b * Cc + nh * 16) * HW + (y0 + py) * Ww + x0 + px;
#pragma unroll
    for (int o = 0; o < 16; o++) {
        float content = 0.f;
#pragma unroll
        for (int i = 0; i < 16; i++) content += qs[i][py][px] * lam[i][o];
        float pos = 0.f;
#pragma unroll
        for (int ky = 0; ky < 5; ky++)
#pragma unroll
            for (int kx = 0; kx < 5; kx++)
                pos += relw[o][ky * 5 + kx] * vs[o][py + ky][px + kx];
        obase[(size_t)o * HW] = content + qs[o][py][px] * pos;
    }
}

// ---------------------------------------------------------------------------
// Launch
// ---------------------------------------------------------------------------
extern "C" void kernel_launch(void* const* d_in, const int* in_sizes, int n_in,
                              void* d_out, int out_size) {
    const float* src      = (const float*)d_in[0];
    const float* cpe_w    = (const float*)d_in[1];
    const float* qkv_w    = (const float*)d_in[2];
    const float* rel_pos  = (const float*)d_in[3];
    const float* conv1d_w = (const float*)d_in[4];
    const float* out_w    = (const float*)d_in[5];
    float* out = (float*)d_out;

    float *s_p, *qkv_p, *lam_p, *pool_p, *w2b_p, *r1_p;
    cudaGetSymbolAddress((void**)&s_p,    g_s);
    cudaGetSymbolAddress((void**)&qkv_p,  g_qkv);
    cudaGetSymbolAddress((void**)&lam_p,  g_lambda);
    cudaGetSymbolAddress((void**)&pool_p, g_pool);
    cudaGetSymbolAddress((void**)&w2b_p,  g_w2b);
    cudaGetSymbolAddress((void**)&r1_p,   g_r1);

    // dynamic smem for 3-stage GEMM: 3*(2560+2176)*4 = 56832 bytes
    const int gemm_smem = 3 * (128 * 20 + 16 * 136) * 4;
    cudaFuncSetAttribute(k_mma_gemm<1>, cudaFuncAttributeMaxDynamicSharedMemorySize, gemm_smem);
    cudaFuncSetAttribute(k_mma_gemm<2>, cudaFuncAttributeMaxDynamicSharedMemorySize, gemm_smem);

    k_cpe<<<Bb * Cc * HW / 1024, 256>>>(src, cpe_w, s_p);
    k_pool<<<Bb * Cc, 256>>>(src, pool_p);
    k_w2b<<<(Bb * OUTC * Cc + 255) / 256, 256>>>(out_w, pool_p, conv1d_w, w2b_p);
    {
        dim3 grid(3 * Cc / 128, HW / 128, Bb);   // mtile fastest -> B-tile L2 reuse
        k_mma_gemm<1><<<grid, 256, gemm_smem>>>(qkv_w, 0, Cc,
                                                s_p, (size_t)Cc * HW,
                                                nullptr, 0, 0, nullptr, 0,
                                                qkv_p, (size_t)3 * Cc * HW);
    }
    {
        dim3 grid(Bb * NHh, 2);
        k_softmax_lambda<<<grid, 256>>>(qkv_p, lam_p);
    }
    {
        dim3 grid(Ww / 16, Hh / 16, Bb * NHh);
        k_result1<<<grid, 256>>>(qkv_p, lam_p, rel_pos, r1_p);
    }
    {
        dim3 grid(OUTC / 128, HW / 128, Bb);     // mtile fastest
        k_mma_gemm<2><<<grid, 256, gemm_smem>>>(out_w, 0, 2 * Cc,
                                                r1_p, (size_t)Cc * HW,
                                                w2b_p, (size_t)OUTC * Cc, Cc,
                                                src, (size_t)Cc * HW,
                                                out, (size_t)OUTC * HW);
    }
}

// round 6
// speedup vs baseline: 1.9243x; 1.0100x over previous
#include <cuda_runtime.h>
#include <cstdint>
#include <cstddef>

#define Bb   16
#define Cc   128
#define Hh   64
#define Ww   64
#define NHh  8
#define HDd  16
#define HW   4096
#define OUTC 512

// ---------------------------------------------------------------------------
// Scratch (tf32 operands stored as float bit-patterns)
// ---------------------------------------------------------------------------
__device__ float g_s[Bb * Cc * HW];          // CPE out, tf32
__device__ float g_srctf[Bb * Cc * HW];      // src, tf32 (for out-GEMM)
__device__ float g_qkv[Bb * 3 * Cc * HW];    // fp32
__device__ float g_lambda[Bb * NHh * HDd * HDd];
__device__ float g_pool[Bb * Cc];            // SUM over HW (zeroed each call)
__device__ float g_w2b[Bb * OUTC * Cc];      // tf32
__device__ float g_r1[Bb * Cc * HW];         // tf32
__device__ float g_wq[3 * Cc * Cc];          // qkv_w, tf32, lda=128
__device__ float g_w1[OUTC * Cc];            // out_w[:, :128], tf32, lda=128

// ---------------------------------------------------------------------------
// helpers
// ---------------------------------------------------------------------------
__device__ __forceinline__ uint32_t f2tf32(float x) {
    uint32_t r;
    asm("cvt.rna.tf32.f32 %0, %1;" : "=r"(r) : "f"(x));
    return r;
}
__device__ __forceinline__ float tf32f(float x) {
    return __uint_as_float(f2tf32(x));
}

__device__ __forceinline__ void mma_tf32(float* c, const uint32_t* a, const uint32_t* b) {
    asm volatile(
        "mma.sync.aligned.m16n8k8.row.col.f32.tf32.tf32.f32 "
        "{%0,%1,%2,%3}, {%4,%5,%6,%7}, {%8,%9}, {%0,%1,%2,%3};\n"
        : "+f"(c[0]), "+f"(c[1]), "+f"(c[2]), "+f"(c[3])
        : "r"(a[0]), "r"(a[1]), "r"(a[2]), "r"(a[3]), "r"(b[0]), "r"(b[1]));
}

__device__ __forceinline__ void cp16(uint32_t smem, const void* gptr) {
    asm volatile("cp.async.cg.shared.global [%0], [%1], 16;\n" :: "r"(smem), "l"(gptr));
}
__device__ __forceinline__ void cp_commit() {
    asm volatile("cp.async.commit_group;\n");
}
template <int N>
__device__ __forceinline__ void cp_wait() {
    asm volatile("cp.async.wait_group %0;\n" :: "n"(N));
}

// ---------------------------------------------------------------------------
// 0) zero the pool accumulator
// ---------------------------------------------------------------------------
__global__ void k_zero(float* __restrict__ pool) {
    int i = blockIdx.x * 256 + threadIdx.x;
    if (i < Bb * Cc) pool[i] = 0.f;
}

// ---------------------------------------------------------------------------
// 1) CPE + src tf32 copy + pool partial sums
// ---------------------------------------------------------------------------
__global__ __launch_bounds__(256) void k_cpe(const float* __restrict__ src,
                                             const float* __restrict__ cpe_w,
                                             float* __restrict__ s,
                                             float* __restrict__ srctf,
                                             float* __restrict__ pool) {
    int gid = blockIdx.x * 256 + threadIdx.x;
    int p4 = gid * 4;
    int x = p4 & 63;
    int h = (p4 >> 6) & 63;
    int c = (p4 >> 12) & 127;
    const float* wp = cpe_w + c * 9;

    float a0 = 0.f, a1 = 0.f, a2 = 0.f, a3 = 0.f;
    float4 ctr = *reinterpret_cast<const float4*>(src + p4);

#pragma unroll
    for (int dy = -1; dy <= 1; dy++) {
        int hy = h + dy;
        if (hy < 0 || hy >= Hh) continue;
        const float* r = src + p4 + dy * Ww;
        float4 m = (dy == 0) ? ctr : *reinterpret_cast<const float4*>(r);
        float lft = (x > 0)  ? r[-1] : 0.f;
        float rgt = (x < 60) ? r[4]  : 0.f;
        float wl = wp[(dy + 1) * 3 + 0];
        float wc = wp[(dy + 1) * 3 + 1];
        float wr = wp[(dy + 1) * 3 + 2];
        a0 += wl * lft + wc * m.x + wr * m.y;
        a1 += wl * m.x + wc * m.y + wr * m.z;
        a2 += wl * m.y + wc * m.z + wr * m.w;
        a3 += wl * m.z + wc * m.w + wr * rgt;
    }
    float4 o = make_float4(tf32f(a0 + ctr.x), tf32f(a1 + ctr.y),
                           tf32f(a2 + ctr.z), tf32f(a3 + ctr.w));
    *reinterpret_cast<float4*>(s + p4) = o;
    float4 st = make_float4(tf32f(ctr.x), tf32f(ctr.y), tf32f(ctr.z), tf32f(ctr.w));
    *reinterpret_cast<float4*>(srctf + p4) = st;

    // pool partial: block covers 1024 consecutive px of one (b,c) plane
    float psum = ctr.x + ctr.y + ctr.z + ctr.w;
    __shared__ float sm[256];
    sm[threadIdx.x] = psum;
    __syncthreads();
    for (int sstep = 128; sstep > 0; sstep >>= 1) {
        if (threadIdx.x < sstep) sm[threadIdx.x] += sm[threadIdx.x + sstep];
        __syncthreads();
    }
    if (threadIdx.x == 0) atomicAdd(&pool[blockIdx.x >> 2], sm[0]);
}

// ---------------------------------------------------------------------------
// 2) weight conversion (qkv_w, out_w[:, :128]) -> tf32, lda=128
// ---------------------------------------------------------------------------
__global__ void k_wconv(const float* __restrict__ qkv_w,
                        const float* __restrict__ out_w,
                        float* __restrict__ wq,
                        float* __restrict__ w1) {
    int idx = blockIdx.x * 256 + threadIdx.x;
    if (idx < 3 * Cc * Cc) {
        wq[idx] = tf32f(qkv_w[idx]);
    } else {
        int i = idx - 3 * Cc * Cc;
        if (i < OUTC * Cc) {
            int o = i >> 7, c = i & 127;
            w1[i] = tf32f(out_w[o * 256 + c]);
        }
    }
}

// ---------------------------------------------------------------------------
// 3) fused ECA + w2b (pool holds SUM -> mean via 1/HW), output tf32
// ---------------------------------------------------------------------------
__global__ __launch_bounds__(256) void k_w2b(const float* __restrict__ out_w,
                                             const float* __restrict__ pool,
                                             const float* __restrict__ conv1d_w,
                                             float* __restrict__ w2b) {
    int idx = blockIdx.x * 256 + threadIdx.x;
    if (idx >= Bb * OUTC * Cc) return;
    int c = idx & 127;
    int o = (idx >> 7) & 511;
    int b = idx >> 16;
    int pc = (b << 7) + c;
    const float inv = 1.0f / HW;
    float left  = (c > 0)   ? pool[pc - 1] * inv : 0.f;
    float mid   = pool[pc] * inv;
    float right = (c < 127) ? pool[pc + 1] * inv : 0.f;
    float z = conv1d_w[0] * left + conv1d_w[1] * mid + conv1d_w[2] * right;
    float ca = 1.0f / (1.0f + __expf(-z));
    w2b[idx] = tf32f(out_w[o * 256 + 128 + c] * ca);
}

// ---------------------------------------------------------------------------
// 4) tf32 GEMM: BM=128, BN=256, BK=16. 8 warps, warp tile 64x64.
//    3-stage cp.async. Operands are pre-converted tf32 (no cvt in loop).
//    All A parts have lda=128. grid (mtile, ntile, batch).
// ---------------------------------------------------------------------------
template <int NPARTS>
__global__ __launch_bounds__(256, 1) void k_mma_gemm(
    const float* __restrict__ A0, size_t sA0,
    const float* __restrict__ B0, size_t sB0,
    const float* __restrict__ A1, size_t sA1,
    const float* __restrict__ B1, size_t sB1,
    float* __restrict__ C, size_t sC) {
    constexpr int BlkM = 128, BlkN = 256, BlkK = 16;
    constexpr int AST = 20;    // conflict-free (checked: banks 20g+t unique)
    constexpr int BST = 264;   // conflict-free (checked: banks 8t+g unique)
    constexpr int ASZ = BlkM * AST;  // 2560
    constexpr int BSZ = BlkK * BST;  // 4224

    extern __shared__ float smbuf[];
    float* Asm = smbuf;
    float* Bsm = smbuf + 3 * ASZ;

    const int tid = threadIdx.x;
    const int bz = blockIdx.z, mtile = blockIdx.x, ntile = blockIdx.y;
    const int warp = tid >> 5, lane = tid & 31;
    const int g = lane >> 2, t = lane & 3;
    const int wm = (warp >> 2) * 64;   // 2 warp-rows
    const int wn = (warp & 3) * 64;    // 4 warp-cols

    auto load_chunk = [&](int cidx, int buf) {
        const int part = (NPARTS == 2) ? (cidx >> 3) : 0;
        const int kin = (cidx & 7) * BlkK;
        const float* Aptr = part ? A1 + (size_t)bz * sA1 : A0 + (size_t)bz * sA0;
        const float* Bptr = part ? B1 + (size_t)bz * sB1 : B0 + (size_t)bz * sB0;
        float* Abuf = Asm + buf * ASZ;
        float* Bbuf = Bsm + buf * BSZ;
#pragma unroll
        for (int i = 0; i < 2; i++) {
            int idx = tid + i * 256;
            int row = idx >> 2, kq = (idx & 3) * 4;
            cp16((uint32_t)__cvta_generic_to_shared(&Abuf[row * AST + kq]),
                 Aptr + (size_t)(mtile * BlkM + row) * 128 + kin + kq);
        }
#pragma unroll
        for (int i = 0; i < 4; i++) {
            int idx = tid + i * 256;
            int kk = idx >> 6, col = (idx & 63) * 4;
            cp16((uint32_t)__cvta_generic_to_shared(&Bbuf[kk * BST + col]),
                 Bptr + (size_t)(kin + kk) * HW + ntile * BlkN + col);
        }
        cp_commit();
    };

    float acc[4][8][4];
#pragma unroll
    for (int f = 0; f < 4; f++)
#pragma unroll
        for (int nf = 0; nf < 8; nf++)
#pragma unroll
            for (int j = 0; j < 4; j++) acc[f][nf][j] = 0.f;

    auto compute = [&](int buf) {
        const uint32_t* Abuf = reinterpret_cast<const uint32_t*>(Asm + buf * ASZ);
        const uint32_t* Bbuf = reinterpret_cast<const uint32_t*>(Bsm + buf * BSZ);
#pragma unroll
        for (int kk = 0; kk < BlkK; kk += 8) {
            uint32_t breg[8][2];
#pragma unroll
            for (int nf = 0; nf < 8; nf++) {
                breg[nf][0] = Bbuf[(kk + t) * BST + wn + nf * 8 + g];
                breg[nf][1] = Bbuf[(kk + t + 4) * BST + wn + nf * 8 + g];
            }
            uint32_t areg[4][4];
#pragma unroll
            for (int f = 0; f < 4; f++) {
                int r0 = wm + f * 16 + g;
                areg[f][0] = Abuf[r0 * AST + kk + t];
                areg[f][1] = Abuf[(r0 + 8) * AST + kk + t];
                areg[f][2] = Abuf[r0 * AST + kk + t + 4];
                areg[f][3] = Abuf[(r0 + 8) * AST + kk + t + 4];
            }
#pragma unroll
            for (int f = 0; f < 4; f++)
#pragma unroll
                for (int nf = 0; nf < 8; nf++)
                    mma_tf32(acc[f][nf], areg[f], breg[nf]);
        }
    };

    const int NC = NPARTS * 8;
    load_chunk(0, 0);
    load_chunk(1, 1);
    for (int cidx = 0; cidx < NC; cidx++) {
        if (cidx < NC - 1) cp_wait<1>(); else cp_wait<0>();
        __syncthreads();
        if (cidx + 2 < NC) load_chunk(cidx + 2, (cidx + 2) % 3);
        compute(cidx % 3);
    }

    float* Cbase = C + (size_t)bz * sC + (size_t)(mtile * BlkM) * HW + ntile * BlkN;
#pragma unroll
    for (int f = 0; f < 4; f++) {
#pragma unroll
        for (int nf = 0; nf < 8; nf++) {
            int row = wm + f * 16 + g;
            int col = wn + nf * 8 + t * 2;
            *reinterpret_cast<float2*>(Cbase + (size_t)row * HW + col) =
                make_float2(acc[f][nf][0], acc[f][nf][1]);
            *reinterpret_cast<float2*>(Cbase + (size_t)(row + 8) * HW + col) =
                make_float2(acc[f][nf][2], acc[f][nf][3]);
        }
    }
}

// ---------------------------------------------------------------------------
// 5) softmax + lambda (v staged through smem)
// ---------------------------------------------------------------------------
__global__ __launch_bounds__(256) void k_softmax_lambda(const float* __restrict__ qkv,
                                                        float* __restrict__ lambda) {
    const int bh = blockIdx.x;
    const int half = blockIdx.y;
    const int b = bh >> 3, nh = bh & 7;
    const float* kbase = qkv + ((size_t)b * 384 + 128 + nh * 16) * HW;
    const float* vbase = qkv + ((size_t)b * 384 + 256 + nh * 16) * HW;
    const int tid = threadIdx.x;
    const int warp = tid >> 5, lane = tid & 31;
    const int i = half * 8 + warp;
    const float* krow = kbase + (size_t)i * HW;

    __shared__ float vsm[16][512];

    float mx = -1e30f;
    for (int n = lane; n < HW; n += 32) mx = fmaxf(mx, krow[n]);
#pragma unroll
    for (int off = 16; off > 0; off >>= 1)
        mx = fmaxf(mx, __shfl_xor_sync(0xffffffff, mx, off));

    float acc[16];
#pragma unroll
    for (int o = 0; o < 16; o++) acc[o] = 0.f;
    float se = 0.f;

    for (int n0 = 0; n0 < HW; n0 += 512) {
        __syncthreads();
        for (int t2 = tid; t2 < 16 * 512; t2 += 256) {
            int o = t2 >> 9, n = t2 & 511;
            vsm[o][n] = vbase[(size_t)o * HW + n0 + n];
        }
        __syncthreads();
#pragma unroll 4
        for (int n = lane; n < 512; n += 32) {
            float e = __expf(krow[n0 + n] - mx);
            se += e;
#pragma unroll
            for (int o = 0; o < 16; o++) acc[o] += e * vsm[o][n];
        }
    }

#pragma unroll
    for (int off = 16; off > 0; off >>= 1) {
        se += __shfl_xor_sync(0xffffffff, se, off);
#pragma unroll
        for (int o = 0; o < 16; o++)
            acc[o] += __shfl_xor_sync(0xffffffff, acc[o], off);
    }
    if (lane == 0) {
        float inv = 0.25f / se;
        float* lp = lambda + (size_t)bh * 256 + i * 16;
#pragma unroll
        for (int o = 0; o < 16; o++) lp[o] = acc[o] * inv;
    }
}

// ---------------------------------------------------------------------------
// 6) result1 = content + q * position_lambda (writes tf32)
// ---------------------------------------------------------------------------
__global__ __launch_bounds__(256) void k_result1(const float* __restrict__ qkv,
                                                 const float* __restrict__ lambda,
                                                 const float* __restrict__ rel_pos,
                                                 float* __restrict__ r1) {
    const int bh = blockIdx.z;
    const int b = bh >> 3, nh = bh & 7;
    const int x0 = blockIdx.x * 16, y0 = blockIdx.y * 16;
    const int tid = threadIdx.x;
    const int px = tid & 15, py = tid >> 4;

    __shared__ float lam[16][16];
    __shared__ float relw[16][25];
    __shared__ float qs[16][16][16];
    __shared__ float vs[16][20][20];

    lam[py][px] = lambda[((size_t)bh * 16 + py) * 16 + px];
    for (int t = tid; t < 400; t += 256) relw[t / 25][t % 25] = rel_pos[t];
    const float* qbase = qkv + ((size_t)b * 384 + nh * 16) * HW;
#pragma unroll
    for (int ch = 0; ch < 16; ch++)
        qs[ch][py][px] = qbase[(size_t)ch * HW + (y0 + py) * Ww + x0 + px];
    const float* vbase = qkv + ((size_t)b * 384 + 256 + nh * 16) * HW;
    for (int t = tid; t < 6400; t += 256) {
        int ch = t / 400;
        int r = t % 400;
        int vy = r / 20, vx = r % 20;
        int gy = y0 + vy - 2, gx = x0 + vx - 2;
        float val = 0.f;
        if (gy >= 0 && gy < Hh && gx >= 0 && gx < Ww)
            val = vbase[(size_t)ch * HW + gy * Ww + gx];
        vs[ch][vy][vx] = val;
    }
    __syncthreads();

    float* obase = r1 + ((size_t)b * Cc + nh * 16) * HW + (y0 + py) * Ww + x0 + px;
#pragma unroll
    for (int o = 0; o < 16; o++) {
        float content = 0.f;
#pragma unroll
        for (int i = 0; i < 16; i++) content += qs[i][py][px] * lam[i][o];
        float pos = 0.f;
#pragma unroll
        for (int ky = 0; ky < 5; ky++)
#pragma unroll
            for (int kx = 0; kx < 5; kx++)
                pos += relw[o][ky * 5 + kx] * vs[o][py + ky][px + kx];
        obase[(size_t)o * HW] = tf32f(content + qs[o][py][px] * pos);
    }
}

// ---------------------------------------------------------------------------
// Launch
// ---------------------------------------------------------------------------
extern "C" void kernel_launch(void* const* d_in, const int* in_sizes, int n_in,
                              void* d_out, int out_size) {
    const float* src      = (const float*)d_in[0];
    const float* cpe_w    = (const float*)d_in[1];
    const float* qkv_w    = (const float*)d_in[2];
    const float* rel_pos  = (const float*)d_in[3];
    const float* conv1d_w = (const float*)d_in[4];
    const float* out_w    = (const float*)d_in[5];
    float* out = (float*)d_out;

    float *s_p, *srctf_p, *qkv_p, *lam_p, *pool_p, *w2b_p, *r1_p, *wq_p, *w1_p;
    cudaGetSymbolAddress((void**)&s_p,     g_s);
    cudaGetSymbolAddress((void**)&srctf_p, g_srctf);
    cudaGetSymbolAddress((void**)&qkv_p,   g_qkv);
    cudaGetSymbolAddress((void**)&lam_p,   g_lambda);
    cudaGetSymbolAddress((void**)&pool_p,  g_pool);
    cudaGetSymbolAddress((void**)&w2b_p,   g_w2b);
    cudaGetSymbolAddress((void**)&r1_p,    g_r1);
    cudaGetSymbolAddress((void**)&wq_p,    g_wq);
    cudaGetSymbolAddress((void**)&w1_p,    g_w1);

    // dynamic smem: 3*(2560+4224)*4 = 81408 bytes
    const int gemm_smem = 3 * (128 * 20 + 16 * 264) * 4;
    cudaFuncSetAttribute(k_mma_gemm<1>, cudaFuncAttributeMaxDynamicSharedMemorySize, gemm_smem);
    cudaFuncSetAttribute(k_mma_gemm<2>, cudaFuncAttributeMaxDynamicSharedMemorySize, gemm_smem);

    k_zero<<<(Bb * Cc + 255) / 256, 256>>>(pool_p);
    k_cpe<<<Bb * Cc * HW / 1024, 256>>>(src, cpe_w, s_p, srctf_p, pool_p);
    k_wconv<<<(3 * Cc * Cc + OUTC * Cc + 255) / 256, 256>>>(qkv_w, out_w, wq_p, w1_p);
    k_w2b<<<(Bb * OUTC * Cc + 255) / 256, 256>>>(out_w, pool_p, conv1d_w, w2b_p);
    {
        dim3 grid(3 * Cc / 128, HW / 256, Bb);   // mtile fastest -> B L2 reuse
        k_mma_gemm<1><<<grid, 256, gemm_smem>>>(wq_p, 0,
                                                s_p, (size_t)Cc * HW,
                                                nullptr, 0, nullptr, 0,
                                                qkv_p, (size_t)3 * Cc * HW);
    }
    {
        dim3 grid(Bb * NHh, 2);
        k_softmax_lambda<<<grid, 256>>>(qkv_p, lam_p);
    }
    {
        dim3 grid(Ww / 16, Hh / 16, Bb * NHh);
        k_result1<<<grid, 256>>>(qkv_p, lam_p, rel_pos, r1_p);
    }
    {
        dim3 grid(OUTC / 128, HW / 256, Bb);
        k_mma_gemm<2><<<grid, 256, gemm_smem>>>(w1_p, 0,
                                                r1_p, (size_t)Cc * HW,
                                                w2b_p, (size_t)OUTC * Cc,
                                                srctf_p, (size_t)Cc * HW,
                                                out, (size_t)OUTC * HW);
    }
}

// round 7
// speedup vs baseline: 2.5214x; 1.3103x over previous
#include <cuda_runtime.h>
#include <cuda_fp16.h>
#include <cstdint>
#include <cstddef>

#define Bb   16
#define Cc   128
#define Hh   64
#define Ww   64
#define NHh  8
#define HDd  16
#define HW   4096
#define OUTC 512

// ---------------------------------------------------------------------------
// Scratch
// ---------------------------------------------------------------------------
__device__ __half g_s[Bb * Cc * HW];          // CPE out, half
__device__ __half g_srch[Bb * Cc * HW];       // src, half
__device__ float  g_qkv[Bb * 3 * Cc * HW];    // fp32
__device__ float  g_lambda[Bb * NHh * HDd * HDd];
__device__ float  g_pool[Bb * Cc];            // SUM over HW
__device__ __half g_w2b[Bb * OUTC * Cc];      // half
__device__ __half g_r1[Bb * Cc * HW];         // half
__device__ __half g_wq[3 * Cc * Cc];          // qkv_w half, lda=128
__device__ __half g_w1[OUTC * Cc];            // out_w[:, :128] half, lda=128

// ---------------------------------------------------------------------------
// helpers
// ---------------------------------------------------------------------------
__device__ __forceinline__ void mma_f16(float* c, const uint32_t* a, const uint32_t* b) {
    asm volatile(
        "mma.sync.aligned.m16n8k16.row.col.f32.f16.f16.f32 "
        "{%0,%1,%2,%3}, {%4,%5,%6,%7}, {%8,%9}, {%0,%1,%2,%3};\n"
        : "+f"(c[0]), "+f"(c[1]), "+f"(c[2]), "+f"(c[3])
        : "r"(a[0]), "r"(a[1]), "r"(a[2]), "r"(a[3]), "r"(b[0]), "r"(b[1]));
}

__device__ __forceinline__ void ldsm_x4(uint32_t* r, uint32_t addr) {
    asm volatile("ldmatrix.sync.aligned.m8n8.x4.shared.b16 {%0,%1,%2,%3}, [%4];"
                 : "=r"(r[0]), "=r"(r[1]), "=r"(r[2]), "=r"(r[3]) : "r"(addr));
}
__device__ __forceinline__ void ldsm_x2t(uint32_t* r, uint32_t addr) {
    asm volatile("ldmatrix.sync.aligned.m8n8.x2.trans.shared.b16 {%0,%1}, [%2];"
                 : "=r"(r[0]), "=r"(r[1]) : "r"(addr));
}

__device__ __forceinline__ void cp16(uint32_t smem, const void* gptr) {
    asm volatile("cp.async.cg.shared.global [%0], [%1], 16;\n" :: "r"(smem), "l"(gptr));
}
__device__ __forceinline__ void cp_commit() {
    asm volatile("cp.async.commit_group;\n");
}
template <int N>
__device__ __forceinline__ void cp_wait() {
    asm volatile("cp.async.wait_group %0;\n" :: "n"(N));
}

// ---------------------------------------------------------------------------
// 0) zero the pool accumulator
// ---------------------------------------------------------------------------
__global__ void k_zero(float* __restrict__ pool) {
    int i = blockIdx.x * 256 + threadIdx.x;
    if (i < Bb * Cc) pool[i] = 0.f;
}

// ---------------------------------------------------------------------------
// 1) CPE (writes half) + src half copy + pool partial sums
// ---------------------------------------------------------------------------
__global__ __launch_bounds__(256) void k_cpe(const float* __restrict__ src,
                                             const float* __restrict__ cpe_w,
                                             __half* __restrict__ s,
                                             __half* __restrict__ srch,
                                             float* __restrict__ pool) {
    int gid = blockIdx.x * 256 + threadIdx.x;
    int p4 = gid * 4;
    int x = p4 & 63;
    int h = (p4 >> 6) & 63;
    int c = (p4 >> 12) & 127;
    const float* wp = cpe_w + c * 9;

    float a0 = 0.f, a1 = 0.f, a2 = 0.f, a3 = 0.f;
    float4 ctr = *reinterpret_cast<const float4*>(src + p4);

#pragma unroll
    for (int dy = -1; dy <= 1; dy++) {
        int hy = h + dy;
        if (hy < 0 || hy >= Hh) continue;
        const float* r = src + p4 + dy * Ww;
        float4 m = (dy == 0) ? ctr : *reinterpret_cast<const float4*>(r);
        float lft = (x > 0)  ? r[-1] : 0.f;
        float rgt = (x < 60) ? r[4]  : 0.f;
        float wl = wp[(dy + 1) * 3 + 0];
        float wc = wp[(dy + 1) * 3 + 1];
        float wr = wp[(dy + 1) * 3 + 2];
        a0 += wl * lft + wc * m.x + wr * m.y;
        a1 += wl * m.x + wc * m.y + wr * m.z;
        a2 += wl * m.y + wc * m.z + wr * m.w;
        a3 += wl * m.z + wc * m.w + wr * rgt;
    }
    __half2* sp = reinterpret_cast<__half2*>(s + p4);
    sp[0] = __floats2half2_rn(a0 + ctr.x, a1 + ctr.y);
    sp[1] = __floats2half2_rn(a2 + ctr.z, a3 + ctr.w);
    __half2* cp = reinterpret_cast<__half2*>(srch + p4);
    cp[0] = __floats2half2_rn(ctr.x, ctr.y);
    cp[1] = __floats2half2_rn(ctr.z, ctr.w);

    float psum = ctr.x + ctr.y + ctr.z + ctr.w;
    __shared__ float sm[256];
    sm[threadIdx.x] = psum;
    __syncthreads();
    for (int sstep = 128; sstep > 0; sstep >>= 1) {
        if (threadIdx.x < sstep) sm[threadIdx.x] += sm[threadIdx.x + sstep];
        __syncthreads();
    }
    if (threadIdx.x == 0) atomicAdd(&pool[blockIdx.x >> 2], sm[0]);
}

// ---------------------------------------------------------------------------
// 2) weight conversion -> half
// ---------------------------------------------------------------------------
__global__ void k_wconv(const float* __restrict__ qkv_w,
                        const float* __restrict__ out_w,
                        __half* __restrict__ wq,
                        __half* __restrict__ w1) {
    int idx = blockIdx.x * 256 + threadIdx.x;
    if (idx < 3 * Cc * Cc) {
        wq[idx] = __float2half_rn(qkv_w[idx]);
    } else {
        int i = idx - 3 * Cc * Cc;
        if (i < OUTC * Cc) {
            int o = i >> 7, c = i & 127;
            w1[i] = __float2half_rn(out_w[o * 256 + c]);
        }
    }
}

// ---------------------------------------------------------------------------
// 3) fused ECA + w2b -> half
// ---------------------------------------------------------------------------
__global__ __launch_bounds__(256) void k_w2b(const float* __restrict__ out_w,
                                             const float* __restrict__ pool,
                                             const float* __restrict__ conv1d_w,
                                             __half* __restrict__ w2b) {
    int idx = blockIdx.x * 256 + threadIdx.x;
    if (idx >= Bb * OUTC * Cc) return;
    int c = idx & 127;
    int o = (idx >> 7) & 511;
    int b = idx >> 16;
    int pc = (b << 7) + c;
    const float inv = 1.0f / HW;
    float left  = (c > 0)   ? pool[pc - 1] * inv : 0.f;
    float mid   = pool[pc] * inv;
    float right = (c < 127) ? pool[pc + 1] * inv : 0.f;
    float z = conv1d_w[0] * left + conv1d_w[1] * mid + conv1d_w[2] * right;
    float ca = 1.0f / (1.0f + __expf(-z));
    w2b[idx] = __float2half_rn(out_w[o * 256 + 128 + c] * ca);
}

// ---------------------------------------------------------------------------
// 4) fp16 GEMM: BM=128, BN=256, BK=16, 8 warps (64x64 warp tile),
//    3-stage cp.async, ldmatrix fragment loads, fp32 accum.
//    C[b] = sum_p A_p[b] (M x 128 half) @ B_p[b] (128 x 4096 half)
// ---------------------------------------------------------------------------
template <int NPARTS>
__global__ __launch_bounds__(256, 1) void k_mma_gemm(
    const __half* __restrict__ A0, size_t sA0,
    const __half* __restrict__ B0, size_t sB0,
    const __half* __restrict__ A1, size_t sA1,
    const __half* __restrict__ B1, size_t sB1,
    float* __restrict__ C, size_t sC) {
    constexpr int BlkM = 128, BlkN = 256, BlkK = 16;
    constexpr int ASTh = 24;    // A smem row stride (halves): 48B -> ldmatrix conflict-free
    constexpr int BSTh = 264;   // B smem row stride (halves): 528B -> conflict-free
    constexpr int ASZh = BlkM * ASTh;  // 3072 halves
    constexpr int BSZh = BlkK * BSTh;  // 4224 halves

    extern __shared__ __half smh[];
    __half* Asm = smh;                 // 3 buffers
    __half* Bsm = smh + 3 * ASZh;      // 3 buffers
    const uint32_t a_base0 = (uint32_t)__cvta_generic_to_shared(Asm);
    const uint32_t b_base0 = (uint32_t)__cvta_generic_to_shared(Bsm);

    const int tid = threadIdx.x;
    const int bz = blockIdx.z, mtile = blockIdx.x, ntile = blockIdx.y;
    const int warp = tid >> 5, lane = tid & 31;
    const int g = lane >> 2, t = lane & 3;
    const int wm = (warp >> 2) * 64;
    const int wn = (warp & 3) * 64;

    auto load_chunk = [&](int cidx, int buf) {
        const int part = (NPARTS == 2) ? (cidx >> 3) : 0;
        const int kin = (cidx & 7) * BlkK;
        const __half* Aptr = part ? A1 + (size_t)bz * sA1 : A0 + (size_t)bz * sA0;
        const __half* Bptr = part ? B1 + (size_t)bz * sB1 : B0 + (size_t)bz * sB0;
        __half* Abuf = Asm + buf * ASZh;
        __half* Bbuf = Bsm + buf * BSZh;
        {   // A: 128 rows x 16 halves; 1 cp16 per thread
            int row = tid >> 1, ho = (tid & 1) * 8;
            cp16((uint32_t)__cvta_generic_to_shared(&Abuf[row * ASTh + ho]),
                 Aptr + (size_t)(mtile * BlkM + row) * 128 + kin + ho);
        }
#pragma unroll
        for (int i = 0; i < 2; i++) {  // B: 16 rows x 256 halves; 2 cp16 per thread
            int idx = tid + i * 256;
            int kk = idx >> 5, col = (idx & 31) * 8;
            cp16((uint32_t)__cvta_generic_to_shared(&Bbuf[kk * BSTh + col]),
                 Bptr + (size_t)(kin + kk) * HW + ntile * BlkN + col);
        }
        cp_commit();
    };

    float acc[4][8][4];
#pragma unroll
    for (int f = 0; f < 4; f++)
#pragma unroll
        for (int nf = 0; nf < 8; nf++)
#pragma unroll
            for (int j = 0; j < 4; j++) acc[f][nf][j] = 0.f;

    // ldmatrix lane-address components (constant per thread)
    const int a_row_in = (lane & 7) + ((lane >> 3) & 1) * 8;  // row within 16
    const int a_kbase  = (lane >> 4) * 8;                     // 0 or 8
    const int b_krow   = lane & 15;                           // k row for B

    auto compute = [&](int buf) {
        const uint32_t a_base = a_base0 + buf * ASZh * 2;
        const uint32_t b_base = b_base0 + buf * BSZh * 2;
        uint32_t areg[4][4];
#pragma unroll
        for (int f = 0; f < 4; f++) {
            uint32_t addr = a_base +
                (uint32_t)(((wm + f * 16 + a_row_in) * ASTh + a_kbase) * 2);
            ldsm_x4(areg[f], addr);
        }
        uint32_t breg[8][2];
#pragma unroll
        for (int nf = 0; nf < 8; nf++) {
            uint32_t addr = b_base +
                (uint32_t)((b_krow * BSTh + wn + nf * 8) * 2);
            ldsm_x2t(breg[nf], addr);
        }
#pragma unroll
        for (int f = 0; f < 4; f++)
#pragma unroll
            for (int nf = 0; nf < 8; nf++)
                mma_f16(acc[f][nf], areg[f], breg[nf]);
    };

    const int NC = NPARTS * 8;
    load_chunk(0, 0);
    load_chunk(1, 1);
    for (int cidx = 0; cidx < NC; cidx++) {
        if (cidx < NC - 1) cp_wait<1>(); else cp_wait<0>();
        __syncthreads();
        if (cidx + 2 < NC) load_chunk(cidx + 2, (cidx + 2) % 3);
        compute(cidx % 3);
    }

    float* Cbase = C + (size_t)bz * sC + (size_t)(mtile * BlkM) * HW + ntile * BlkN;
#pragma unroll
    for (int f = 0; f < 4; f++) {
#pragma unroll
        for (int nf = 0; nf < 8; nf++) {
            int row = wm + f * 16 + g;
            int col = wn + nf * 8 + t * 2;
            *reinterpret_cast<float2*>(Cbase + (size_t)row * HW + col) =
                make_float2(acc[f][nf][0], acc[f][nf][1]);
            *reinterpret_cast<float2*>(Cbase + (size_t)(row + 8) * HW + col) =
                make_float2(acc[f][nf][2], acc[f][nf][3]);
        }
    }
}

// ---------------------------------------------------------------------------
// 5) softmax + lambda (v staged through smem)
// ---------------------------------------------------------------------------
__global__ __launch_bounds__(256) void k_softmax_lambda(const float* __restrict__ qkv,
                                                        float* __restrict__ lambda) {
    const int bh = blockIdx.x;
    const int half = blockIdx.y;
    const int b = bh >> 3, nh = bh & 7;
    const float* kbase = qkv + ((size_t)b * 384 + 128 + nh * 16) * HW;
    const float* vbase = qkv + ((size_t)b * 384 + 256 + nh * 16) * HW;
    const int tid = threadIdx.x;
    const int warp = tid >> 5, lane = tid & 31;
    const int i = half * 8 + warp;
    const float* krow = kbase + (size_t)i * HW;

    __shared__ float vsm[16][512];

    float mx = -1e30f;
    for (int n = lane; n < HW; n += 32) mx = fmaxf(mx, krow[n]);
#pragma unroll
    for (int off = 16; off > 0; off >>= 1)
        mx = fmaxf(mx, __shfl_xor_sync(0xffffffff, mx, off));

    float acc[16];
#pragma unroll
    for (int o = 0; o < 16; o++) acc[o] = 0.f;
    float se = 0.f;

    for (int n0 = 0; n0 < HW; n0 += 512) {
        __syncthreads();
        for (int t2 = tid; t2 < 16 * 512; t2 += 256) {
            int o = t2 >> 9, n = t2 & 511;
            vsm[o][n] = vbase[(size_t)o * HW + n0 + n];
        }
        __syncthreads();
#pragma unroll 4
        for (int n = lane; n < 512; n += 32) {
            float e = __expf(krow[n0 + n] - mx);
            se += e;
#pragma unroll
            for (int o = 0; o < 16; o++) acc[o] += e * vsm[o][n];
        }
    }

#pragma unroll
    for (int off = 16; off > 0; off >>= 1) {
        se += __shfl_xor_sync(0xffffffff, se, off);
#pragma unroll
        for (int o = 0; o < 16; o++)
            acc[o] += __shfl_xor_sync(0xffffffff, acc[o], off);
    }
    if (lane == 0) {
        float inv = 0.25f / se;
        float* lp = lambda + (size_t)bh * 256 + i * 16;
#pragma unroll
        for (int o = 0; o < 16; o++) lp[o] = acc[o] * inv;
    }
}

// ---------------------------------------------------------------------------
// 6) result1 = content + q * position_lambda (writes half)
// ---------------------------------------------------------------------------
__global__ __launch_bounds__(256) void k_result1(const float* __restrict__ qkv,
                                                 const float* __restrict__ lambda,
                                                 const float* __restrict__ rel_pos,
                                                 __half* __restrict__ r1) {
    const int bh = blockIdx.z;
    const int b = bh >> 3, nh = bh & 7;
    const int x0 = blockIdx.x * 16, y0 = blockIdx.y * 16;
    const int tid = threadIdx.x;
    const int px = tid & 15, py = tid >> 4;

    __shared__ float lam[16][16];
    __shared__ float relw[16][25];
    __shared__ float qs[16][16][16];
    __shared__ float vs[16][20][20];

    lam[py][px] = lambda[((size_t)bh * 16 + py) * 16 + px];
    for (int t = tid; t < 400; t += 256) relw[t / 25][t % 25] = rel_pos[t];
    const float* qbase = qkv + ((size_t)b * 384 + nh * 16) * HW;
#pragma unroll
    for (int ch = 0; ch < 16; ch++)
        qs[ch][py][px] = qbase[(size_t)ch * HW + (y0 + py) * Ww + x0 + px];
    const float* vbase = qkv + ((size_t)b * 384 + 256 + nh * 16) * HW;
    for (int t = tid; t < 6400; t += 256) {
        int ch = t / 400;
        int r = t % 400;
        int vy = r / 20, vx = r % 20;
        int gy = y0 + vy - 2, gx = x0 + vx - 2;
        float val = 0.f;
        if (gy >= 0 && gy < Hh && gx >= 0 && gx < Ww)
            val = vbase[(size_t)ch * HW + gy * Ww + gx];
        vs[ch][vy][vx] = val;
    }
    __syncthreads();

    __half* obase = r1 + ((size_t)b * Cc + nh * 16) * HW + (y0 + py) * Ww + x0 + px;
#pragma unroll
    for (int o = 0; o < 16; o++) {
        float content = 0.f;
#pragma unroll
        for (int i = 0; i < 16; i++) content += qs[i][py][px] * lam[i][o];
        float pos = 0.f;
#pragma unroll
        for (int ky = 0; ky < 5; ky++)
#pragma unroll
            for (int kx = 0; kx < 5; kx++)
                pos += relw[o][ky * 5 + kx] * vs[o][py + ky][px + kx];
        obase[(size_t)o * HW] = __float2half_rn(content + qs[o][py][px] * pos);
    }
}

// ---------------------------------------------------------------------------
// Launch
// ---------------------------------------------------------------------------
extern "C" void kernel_launch(void* const* d_in, const int* in_sizes, int n_in,
                              void* d_out, int out_size) {
    const float* src      = (const float*)d_in[0];
    const float* cpe_w    = (const float*)d_in[1];
    const float* qkv_w    = (const float*)d_in[2];
    const float* rel_pos  = (const float*)d_in[3];
    const float* conv1d_w = (const float*)d_in[4];
    const float* out_w    = (const float*)d_in[5];
    float* out = (float*)d_out;

    __half *s_p, *srch_p, *w2b_p, *r1_p, *wq_p, *w1_p;
    float *qkv_p, *lam_p, *pool_p;
    cudaGetSymbolAddress((void**)&s_p,    g_s);
    cudaGetSymbolAddress((void**)&srch_p, g_srch);
    cudaGetSymbolAddress((void**)&qkv_p,  g_qkv);
    cudaGetSymbolAddress((void**)&lam_p,  g_lambda);
    cudaGetSymbolAddress((void**)&pool_p, g_pool);
    cudaGetSymbolAddress((void**)&w2b_p,  g_w2b);
    cudaGetSymbolAddress((void**)&r1_p,   g_r1);
    cudaGetSymbolAddress((void**)&wq_p,   g_wq);
    cudaGetSymbolAddress((void**)&w1_p,   g_w1);

    // dynamic smem: 3*(3072+4224) halves * 2B = 43776 bytes
    const int gemm_smem = 3 * (128 * 24 + 16 * 264) * 2;
    cudaFuncSetAttribute(k_mma_gemm<1>, cudaFuncAttributeMaxDynamicSharedMemorySize, gemm_smem);
    cudaFuncSetAttribute(k_mma_gemm<2>, cudaFuncAttributeMaxDynamicSharedMemorySize, gemm_smem);

    k_zero<<<(Bb * Cc + 255) / 256, 256>>>(pool_p);
    k_cpe<<<Bb * Cc * HW / 1024, 256>>>(src, cpe_w, s_p, srch_p, pool_p);
    k_wconv<<<(3 * Cc * Cc + OUTC * Cc + 255) / 256, 256>>>(qkv_w, out_w, wq_p, w1_p);
    k_w2b<<<(Bb * OUTC * Cc + 255) / 256, 256>>>(out_w, pool_p, conv1d_w, w2b_p);
    {
        dim3 grid(3 * Cc / 128, HW / 256, Bb);   // mtile fastest -> B L2 reuse
        k_mma_gemm<1><<<grid, 256, gemm_smem>>>(wq_p, 0,
                                                s_p, (size_t)Cc * HW,
                                                nullptr, 0, nullptr, 0,
                                                qkv_p, (size_t)3 * Cc * HW);
    }
    {
        dim3 grid(Bb * NHh, 2);
        k_softmax_lambda<<<grid, 256>>>(qkv_p, lam_p);
    }
    {
        dim3 grid(Ww / 16, Hh / 16, Bb * NHh);
        k_result1<<<grid, 256>>>(qkv_p, lam_p, rel_pos, r1_p);
    }
    {
        dim3 grid(OUTC / 128, HW / 256, Bb);
        k_mma_gemm<2><<<grid, 256, gemm_smem>>>(w1_p, 0,
                                                r1_p, (size_t)Cc * HW,
                                                w2b_p, (size_t)OUTC * Cc,
                                                srch_p, (size_t)Cc * HW,
                                                out, (size_t)OUTC * HW);
    }
}

// round 9
// speedup vs baseline: 2.8391x; 1.1260x over previous
#include <cuda_runtime.h>
#include <cuda_fp16.h>
#include <cstdint>
#include <cstddef>

#define Bb   16
#define Cc   128
#define Hh   64
#define Ww   64
#define NHh  8
#define HDd  16
#define HW   4096
#define OUTC 512

// ---------------------------------------------------------------------------
// Scratch
// ---------------------------------------------------------------------------
__device__ __half g_s[Bb * Cc * HW];          // CPE out, half
__device__ __half g_srch[Bb * Cc * HW];       // src, half
__device__ __half g_qkv[Bb * 3 * Cc * HW];    // qkv, half
__device__ float  g_lambda[Bb * NHh * HDd * HDd];
__device__ float  g_pool[Bb * Cc];
__device__ __half g_w2b[Bb * OUTC * Cc];      // half, lda=128
__device__ __half g_r1[Bb * Cc * HW];         // half
__device__ __half g_wq[3 * Cc * Cc];          // qkv_w half, lda=128
__device__ __half g_w1[OUTC * Cc];            // out_w[:, :128] half, lda=128

// ---------------------------------------------------------------------------
// helpers
// ---------------------------------------------------------------------------
__device__ __forceinline__ void mma_f16(float* c, const uint32_t* a, const uint32_t* b) {
    asm volatile(
        "mma.sync.aligned.m16n8k16.row.col.f32.f16.f16.f32 "
        "{%0,%1,%2,%3}, {%4,%5,%6,%7}, {%8,%9}, {%0,%1,%2,%3};\n"
        : "+f"(c[0]), "+f"(c[1]), "+f"(c[2]), "+f"(c[3])
        : "r"(a[0]), "r"(a[1]), "r"(a[2]), "r"(a[3]), "r"(b[0]), "r"(b[1]));
}

__device__ __forceinline__ void ldsm_x4(uint32_t* r, uint32_t addr) {
    asm volatile("ldmatrix.sync.aligned.m8n8.x4.shared.b16 {%0,%1,%2,%3}, [%4];"
                 : "=r"(r[0]), "=r"(r[1]), "=r"(r[2]), "=r"(r[3]) : "r"(addr));
}
__device__ __forceinline__ void ldsm_x2t(uint32_t* r, uint32_t addr) {
    asm volatile("ldmatrix.sync.aligned.m8n8.x2.trans.shared.b16 {%0,%1}, [%2];"
                 : "=r"(r[0]), "=r"(r[1]) : "r"(addr));
}

__device__ __forceinline__ void cp16(uint32_t smem, const void* gptr) {
    asm volatile("cp.async.cg.shared.global [%0], [%1], 16;\n" :: "r"(smem), "l"(gptr));
}
__device__ __forceinline__ void cp_commit() {
    asm volatile("cp.async.commit_group;\n");
}
template <int N>
__device__ __forceinline__ void cp_wait() {
    asm volatile("cp.async.wait_group %0;\n" :: "n"(N));
}

// epilogue store: half or float
__device__ __forceinline__ void store2(__half* p, float a, float b) {
    *reinterpret_cast<__half2*>(p) = __floats2half2_rn(a, b);
}
__device__ __forceinline__ void store2(float* p, float a, float b) {
    *reinterpret_cast<float2*>(p) = make_float2(a, b);
}

// ---------------------------------------------------------------------------
// 0) zero the pool accumulator
// ---------------------------------------------------------------------------
__global__ void k_zero(float* __restrict__ pool) {
    int i = blockIdx.x * 256 + threadIdx.x;
    if (i < Bb * Cc) pool[i] = 0.f;
}

// ---------------------------------------------------------------------------
// 1) CPE (half out) + src half copy + pool partial sums
// ---------------------------------------------------------------------------
__global__ __launch_bounds__(256) void k_cpe(const float* __restrict__ src,
                                             const float* __restrict__ cpe_w,
                                             __half* __restrict__ s,
                                             __half* __restrict__ srch,
                                             float* __restrict__ pool) {
    int gid = blockIdx.x * 256 + threadIdx.x;
    int p4 = gid * 4;
    int x = p4 & 63;
    int h = (p4 >> 6) & 63;
    int c = (p4 >> 12) & 127;
    const float* wp = cpe_w + c * 9;

    float a0 = 0.f, a1 = 0.f, a2 = 0.f, a3 = 0.f;
    float4 ctr = *reinterpret_cast<const float4*>(src + p4);

#pragma unroll
    for (int dy = -1; dy <= 1; dy++) {
        int hy = h + dy;
        if (hy < 0 || hy >= Hh) continue;
        const float* r = src + p4 + dy * Ww;
        float4 m = (dy == 0) ? ctr : *reinterpret_cast<const float4*>(r);
        float lft = (x > 0)  ? r[-1] : 0.f;
        float rgt = (x < 60) ? r[4]  : 0.f;
        float wl = wp[(dy + 1) * 3 + 0];
        float wc = wp[(dy + 1) * 3 + 1];
        float wr = wp[(dy + 1) * 3 + 2];
        a0 += wl * lft + wc * m.x + wr * m.y;
        a1 += wl * m.x + wc * m.y + wr * m.z;
        a2 += wl * m.y + wc * m.z + wr * m.w;
        a3 += wl * m.z + wc * m.w + wr * rgt;
    }
    __half2* sp = reinterpret_cast<__half2*>(s + p4);
    sp[0] = __floats2half2_rn(a0 + ctr.x, a1 + ctr.y);
    sp[1] = __floats2half2_rn(a2 + ctr.z, a3 + ctr.w);
    __half2* cph = reinterpret_cast<__half2*>(srch + p4);
    cph[0] = __floats2half2_rn(ctr.x, ctr.y);
    cph[1] = __floats2half2_rn(ctr.z, ctr.w);

    float psum = ctr.x + ctr.y + ctr.z + ctr.w;
    __shared__ float sm[256];
    sm[threadIdx.x] = psum;
    __syncthreads();
    for (int sstep = 128; sstep > 0; sstep >>= 1) {
        if (threadIdx.x < sstep) sm[threadIdx.x] += sm[threadIdx.x + sstep];
        __syncthreads();
    }
    if (threadIdx.x == 0) atomicAdd(&pool[blockIdx.x >> 2], sm[0]);
}

// ---------------------------------------------------------------------------
// 2) weight conversion -> half
// ---------------------------------------------------------------------------
__global__ void k_wconv(const float* __restrict__ qkv_w,
                        const float* __restrict__ out_w,
                        __half* __restrict__ wq,
                        __half* __restrict__ w1) {
    int idx = blockIdx.x * 256 + threadIdx.x;
    if (idx < 3 * Cc * Cc) {
        wq[idx] = __float2half_rn(qkv_w[idx]);
    } else {
        int i = idx - 3 * Cc * Cc;
        if (i < OUTC * Cc) {
            int o = i >> 7, c = i & 127;
            w1[i] = __float2half_rn(out_w[o * 256 + c]);
        }
    }
}

// ---------------------------------------------------------------------------
// 3) fused ECA + w2b -> half
// ---------------------------------------------------------------------------
__global__ __launch_bounds__(256) void k_w2b(const float* __restrict__ out_w,
                                             const float* __restrict__ pool,
                                             const float* __restrict__ conv1d_w,
                                             __half* __restrict__ w2b) {
    int idx = blockIdx.x * 256 + threadIdx.x;
    if (idx >= Bb * OUTC * Cc) return;
    int c = idx & 127;
    int o = (idx >> 7) & 511;
    int b = idx >> 16;
    int pc = (b << 7) + c;
    const float inv = 1.0f / HW;
    float left  = (c > 0)   ? pool[pc - 1] * inv : 0.f;
    float mid   = pool[pc] * inv;
    float right = (c < 127) ? pool[pc + 1] * inv : 0.f;
    float z = conv1d_w[0] * left + conv1d_w[1] * mid + conv1d_w[2] * right;
    float ca = 1.0f / (1.0f + __expf(-z));
    w2b[idx] = __float2half_rn(out_w[o * 256 + 128 + c] * ca);
}

// ---------------------------------------------------------------------------
// 4) fp16 GEMM: BM=128, BN=256, BK=16, 8 warps (64x64 warp tile),
//    3-stage cp.async, ldmatrix fragment loads, fp32 accum, OutT epilogue.
// ---------------------------------------------------------------------------
template <int NPARTS, typename OutT>
__global__ __launch_bounds__(256, 1) void k_mma_gemm(
    const __half* __restrict__ A0, size_t sA0,
    const __half* __restrict__ B0, size_t sB0,
    const __half* __restrict__ A1, size_t sA1,
    const __half* __restrict__ B1, size_t sB1,
    OutT* __restrict__ C, size_t sC) {
    constexpr int BlkM = 128, BlkN = 256, BlkK = 16;
    constexpr int ASTh = 24;
    constexpr int BSTh = 264;
    constexpr int ASZh = BlkM * ASTh;
    constexpr int BSZh = BlkK * BSTh;

    extern __shared__ __half smh[];
    __half* Asm = smh;
    __half* Bsm = smh + 3 * ASZh;
    const uint32_t a_base0 = (uint32_t)__cvta_generic_to_shared(Asm);
    const uint32_t b_base0 = (uint32_t)__cvta_generic_to_shared(Bsm);

    const int tid = threadIdx.x;
    const int bz = blockIdx.z, mtile = blockIdx.x, ntile = blockIdx.y;
    const int warp = tid >> 5, lane = tid & 31;
    const int g = lane >> 2, t = lane & 3;
    const int wm = (warp >> 2) * 64;
    const int wn = (warp & 3) * 64;

    auto load_chunk = [&](int cidx, int buf) {
        const int part = (NPARTS == 2) ? (cidx >> 3) : 0;
        const int kin = (cidx & 7) * BlkK;
        const __half* Aptr = part ? A1 + (size_t)bz * sA1 : A0 + (size_t)bz * sA0;
        const __half* Bptr = part ? B1 + (size_t)bz * sB1 : B0 + (size_t)bz * sB0;
        __half* Abuf = Asm + buf * ASZh;
        __half* Bbuf = Bsm + buf * BSZh;
        {
            int row = tid >> 1, ho = (tid & 1) * 8;
            cp16((uint32_t)__cvta_generic_to_shared(&Abuf[row * ASTh + ho]),
                 Aptr + (size_t)(mtile * BlkM + row) * 128 + kin + ho);
        }
#pragma unroll
        for (int i = 0; i < 2; i++) {
            int idx = tid + i * 256;
            int kk = idx >> 5, col = (idx & 31) * 8;
            cp16((uint32_t)__cvta_generic_to_shared(&Bbuf[kk * BSTh + col]),
                 Bptr + (size_t)(kin + kk) * HW + ntile * BlkN + col);
        }
        cp_commit();
    };

    float acc[4][8][4];
#pragma unroll
    for (int f = 0; f < 4; f++)
#pragma unroll
        for (int nf = 0; nf < 8; nf++)
#pragma unroll
            for (int j = 0; j < 4; j++) acc[f][nf][j] = 0.f;

    const int a_row_in = (lane & 7) + ((lane >> 3) & 1) * 8;
    const int a_kbase  = (lane >> 4) * 8;
    const int b_krow   = lane & 15;

    auto compute = [&](int buf) {
        const uint32_t a_base = a_base0 + buf * ASZh * 2;
        const uint32_t b_base = b_base0 + buf * BSZh * 2;
        uint32_t areg[4][4];
#pragma unroll
        for (int f = 0; f < 4; f++) {
            uint32_t addr = a_base +
                (uint32_t)(((wm + f * 16 + a_row_in) * ASTh + a_kbase) * 2);
            ldsm_x4(areg[f], addr);
        }
        uint32_t breg[8][2];
#pragma unroll
        for (int nf = 0; nf < 8; nf++) {
            uint32_t addr = b_base +
                (uint32_t)((b_krow * BSTh + wn + nf * 8) * 2);
            ldsm_x2t(breg[nf], addr);
        }
#pragma unroll
        for (int f = 0; f < 4; f++)
#pragma unroll
            for (int nf = 0; nf < 8; nf++)
                mma_f16(acc[f][nf], areg[f], breg[nf]);
    };

    const int NC = NPARTS * 8;
    load_chunk(0, 0);
    load_chunk(1, 1);
    for (int cidx = 0; cidx < NC; cidx++) {
        if (cidx < NC - 1) cp_wait<1>(); else cp_wait<0>();
        __syncthreads();
        if (cidx + 2 < NC) load_chunk(cidx + 2, (cidx + 2) % 3);
        compute(cidx % 3);
    }

    OutT* Cbase = C + (size_t)bz * sC + (size_t)(mtile * BlkM) * HW + ntile * BlkN;
#pragma unroll
    for (int f = 0; f < 4; f++) {
#pragma unroll
        for (int nf = 0; nf < 8; nf++) {
            int row = wm + f * 16 + g;
            int col = wn + nf * 8 + t * 2;
            store2(Cbase + (size_t)row * HW + col, acc[f][nf][0], acc[f][nf][1]);
            store2(Cbase + (size_t)(row + 8) * HW + col, acc[f][nf][2], acc[f][nf][3]);
        }
    }
}

// ---------------------------------------------------------------------------
// 5) softmax + lambda (qkv in half; fp32 math, v staged through smem)
// ---------------------------------------------------------------------------
__global__ __launch_bounds__(256) void k_softmax_lambda(const __half* __restrict__ qkv,
                                                        float* __restrict__ lambda) {
    const int bh = blockIdx.x;
    const int hlf = blockIdx.y;
    const int b = bh >> 3, nh = bh & 7;
    const __half* kbase = qkv + ((size_t)b * 384 + 128 + nh * 16) * HW;
    const __half* vbase = qkv + ((size_t)b * 384 + 256 + nh * 16) * HW;
    const int tid = threadIdx.x;
    const int warp = tid >> 5, lane = tid & 31;
    const int i = hlf * 8 + warp;
    const __half* krow = kbase + (size_t)i * HW;

    __shared__ float vsm[16][512];

    float mx = -1e30f;
    for (int n = lane; n < HW; n += 32) mx = fmaxf(mx, __half2float(krow[n]));
#pragma unroll
    for (int off = 16; off > 0; off >>= 1)
        mx = fmaxf(mx, __shfl_xor_sync(0xffffffff, mx, off));

    float acc[16];
#pragma unroll
    for (int o = 0; o < 16; o++) acc[o] = 0.f;
    float se = 0.f;

    for (int n0 = 0; n0 < HW; n0 += 512) {
        __syncthreads();
        for (int t2 = tid; t2 < 16 * 256; t2 += 256) {
            int o = t2 >> 8, n2 = (t2 & 255) * 2;
            __half2 hv = *reinterpret_cast<const __half2*>(vbase + (size_t)o * HW + n0 + n2);
            vsm[o][n2]     = __low2float(hv);
            vsm[o][n2 + 1] = __high2float(hv);
        }
        __syncthreads();
#pragma unroll 4
        for (int n = lane; n < 512; n += 32) {
            float e = __expf(__half2float(krow[n0 + n]) - mx);
            se += e;
#pragma unroll
            for (int o = 0; o < 16; o++) acc[o] += e * vsm[o][n];
        }
    }

#pragma unroll
    for (int off = 16; off > 0; off >>= 1) {
        se += __shfl_xor_sync(0xffffffff, se, off);
#pragma unroll
        for (int o = 0; o < 16; o++)
            acc[o] += __shfl_xor_sync(0xffffffff, acc[o], off);
    }
    if (lane == 0) {
        float inv = 0.25f / se;
        float* lp = lambda + (size_t)bh * 256 + i * 16;
#pragma unroll
        for (int o = 0; o < 16; o++) lp[o] = acc[o] * inv;
    }
}

// ---------------------------------------------------------------------------
// 6) result1 = content + q * position_lambda (qkv half in, half out)
// ---------------------------------------------------------------------------
__global__ __launch_bounds__(256) void k_result1(const __half* __restrict__ qkv,
                                                 const float* __restrict__ lambda,
                                                 const float* __restrict__ rel_pos,
                                                 __half* __restrict__ r1) {
    const int bh = blockIdx.z;
    const int b = bh >> 3, nh = bh & 7;
    const int x0 = blockIdx.x * 16, y0 = blockIdx.y * 16;
    const int tid = threadIdx.x;
    const int px = tid & 15, py = tid >> 4;

    __shared__ float lam[16][16];
    __shared__ float relw[16][25];
    __shared__ float qs[16][16][16];
    __shared__ float vs[16][20][20];

    lam[py][px] = lambda[((size_t)bh * 16 + py) * 16 + px];
    for (int t = tid; t < 400; t += 256) relw[t / 25][t % 25] = rel_pos[t];
    const __half* qbase = qkv + ((size_t)b * 384 + nh * 16) * HW;
#pragma unroll
    for (int ch = 0; ch < 16; ch++)
        qs[ch][py][px] = __half2float(qbase[(size_t)ch * HW + (y0 + py) * Ww + x0 + px]);
    const __half* vbase = qkv + ((size_t)b * 384 + 256 + nh * 16) * HW;
    for (int t = tid; t < 6400; t += 256) {
        int ch = t / 400;
        int r = t % 400;
        int vy = r / 20, vx = r % 20;
        int gy = y0 + vy - 2, gx = x0 + vx - 2;
        float val = 0.f;
        if (gy >= 0 && gy < Hh && gx >= 0 && gx < Ww)
            val = __half2float(vbase[(size_t)ch * HW + gy * Ww + gx]);
        vs[ch][vy][vx] = val;
    }
    __syncthreads();

    __half* obase = r1 + ((size_t)b * Cc + nh * 16) * HW + (y0 + py) * Ww + x0 + px;
#pragma unroll
    for (int o = 0; o < 16; o++) {
        float content = 0.f;
#pragma unroll
        for (int i = 0; i < 16; i++) content += qs[i][py][px] * lam[i][o];
        float pos = 0.f;
#pragma unroll
        for (int ky = 0; ky < 5; ky++)
#pragma unroll
            for (int kx = 0; kx < 5; kx++)
                pos += relw[o][ky * 5 + kx] * vs[o][py + ky][px + kx];
        obase[(size_t)o * HW] = __float2half_rn(content + qs[o][py][px] * pos);
    }
}

// ---------------------------------------------------------------------------
// Launch
// ---------------------------------------------------------------------------
extern "C" void kernel_launch(void* const* d_in, const int* in_sizes, int n_in,
                              void* d_out, int out_size) {
    const float* src      = (const float*)d_in[0];
    const float* cpe_w    = (const float*)d_in[1];
    const float* qkv_w    = (const float*)d_in[2];
    const float* rel_pos  = (const float*)d_in[3];
    const float* conv1d_w = (const float*)d_in[4];
    const float* out_w    = (const float*)d_in[5];
    float* out = (float*)d_out;

    __half *s_p, *srch_p, *qkv_p, *w2b_p, *r1_p, *wq_p, *w1_p;
    float *lam_p, *pool_p;
    cudaGetSymbolAddress((void**)&s_p,    g_s);
    cudaGetSymbolAddress((void**)&srch_p, g_srch);
    cudaGetSymbolAddress((void**)&qkv_p,  g_qkv);
    cudaGetSymbolAddress((void**)&lam_p,  g_lambda);
    cudaGetSymbolAddress((void**)&pool_p, g_pool);
    cudaGetSymbolAddress((void**)&w2b_p,  g_w2b);
    cudaGetSymbolAddress((void**)&r1_p,   g_r1);
    cudaGetSymbolAddress((void**)&wq_p,   g_wq);
    cudaGetSymbolAddress((void**)&w1_p,   g_w1);

    const int gemm_smem = 3 * (128 * 24 + 16 * 264) * 2;  // 43776 bytes
    cudaFuncSetAttribute(k_mma_gemm<1, __half>, cudaFuncAttributeMaxDynamicSharedMemorySize, gemm_smem);
    cudaFuncSetAttribute(k_mma_gemm<2, float>,  cudaFuncAttributeMaxDynamicSharedMemorySize, gemm_smem);

    k_zero<<<(Bb * Cc + 255) / 256, 256>>>(pool_p);
    k_cpe<<<Bb * Cc * HW / 1024, 256>>>(src, cpe_w, s_p, srch_p, pool_p);
    k_wconv<<<(3 * Cc * Cc + OUTC * Cc + 255) / 256, 256>>>(qkv_w, out_w, wq_p, w1_p);
    k_w2b<<<(Bb * OUTC * Cc + 255) / 256, 256>>>(out_w, pool_p, conv1d_w, w2b_p);
    {
        dim3 grid(3 * Cc / 128, HW / 256, Bb);
        k_mma_gemm<1, __half><<<grid, 256, gemm_smem>>>(wq_p, 0,
                                                        s_p, (size_t)Cc * HW,
                                                        nullptr, 0, nullptr, 0,
                                                        qkv_p, (size_t)3 * Cc * HW);
    }
    {
        dim3 grid(Bb * NHh, 2);
        k_softmax_lambda<<<grid, 256>>>(qkv_p, lam_p);
    }
    {
        dim3 grid(Ww / 16, Hh / 16, Bb * NHh);
        k_result1<<<grid, 256>>>(qkv_p, lam_p, rel_pos, r1_p);
    }
    {
        dim3 grid(OUTC / 128, HW / 256, Bb);
        k_mma_gemm<2, float><<<grid, 256, gemm_smem>>>(w1_p, 0,
                                                       r1_p, (size_t)Cc * HW,
                                                       w2b_p, (size_t)OUTC * Cc,
                                                       srch_p, (size_t)Cc * HW,
                                                       out, (size_t)OUTC * HW);
    }
}

// round 10
// speedup vs baseline: 2.8943x; 1.0194x over previous
#include <cuda_runtime.h>
#include <cuda_fp16.h>
#include <cstdint>
#include <cstddef>

#define Bb   16
#define Cc   128
#define Hh   64
#define Ww   64
#define NHh  8
#define HDd  16
#define HW   4096
#define OUTC 512

// ---------------------------------------------------------------------------
// Scratch
// ---------------------------------------------------------------------------
__device__ __half g_s[Bb * Cc * HW];          // CPE out, half
__device__ __half g_srch[Bb * Cc * HW];       // src, half
__device__ __half g_qkv[Bb * 3 * Cc * HW];    // qkv, half
__device__ float  g_lambda[Bb * NHh * HDd * HDd];
__device__ float  g_poolpart[Bb * Cc * 4];    // per-quarter partial sums
__device__ __half g_w2b[Bb * OUTC * Cc];      // half, lda=128
__device__ __half g_r1[Bb * Cc * HW];         // half
__device__ __half g_wq[3 * Cc * Cc];          // qkv_w half, lda=128
__device__ __half g_w1[OUTC * Cc];            // out_w[:, :128] half, lda=128

// ---------------------------------------------------------------------------
// helpers
// ---------------------------------------------------------------------------
__device__ __forceinline__ void mma_f16(float* c, const uint32_t* a, const uint32_t* b) {
    asm volatile(
        "mma.sync.aligned.m16n8k16.row.col.f32.f16.f16.f32 "
        "{%0,%1,%2,%3}, {%4,%5,%6,%7}, {%8,%9}, {%0,%1,%2,%3};\n"
        : "+f"(c[0]), "+f"(c[1]), "+f"(c[2]), "+f"(c[3])
        : "r"(a[0]), "r"(a[1]), "r"(a[2]), "r"(a[3]), "r"(b[0]), "r"(b[1]));
}

__device__ __forceinline__ void ldsm_x4(uint32_t* r, uint32_t addr) {
    asm volatile("ldmatrix.sync.aligned.m8n8.x4.shared.b16 {%0,%1,%2,%3}, [%4];"
                 : "=r"(r[0]), "=r"(r[1]), "=r"(r[2]), "=r"(r[3]) : "r"(addr));
}
__device__ __forceinline__ void ldsm_x2t(uint32_t* r, uint32_t addr) {
    asm volatile("ldmatrix.sync.aligned.m8n8.x2.trans.shared.b16 {%0,%1}, [%2];"
                 : "=r"(r[0]), "=r"(r[1]) : "r"(addr));
}

__device__ __forceinline__ void cp16(uint32_t smem, const void* gptr) {
    asm volatile("cp.async.cg.shared.global [%0], [%1], 16;\n" :: "r"(smem), "l"(gptr));
}
__device__ __forceinline__ void cp_commit() {
    asm volatile("cp.async.commit_group;\n");
}
template <int N>
__device__ __forceinline__ void cp_wait() {
    asm volatile("cp.async.wait_group %0;\n" :: "n"(N));
}

__device__ __forceinline__ void store2(__half* p, float a, float b) {
    *reinterpret_cast<__half2*>(p) = __floats2half2_rn(a, b);
}
__device__ __forceinline__ void store2(float* p, float a, float b) {
    *reinterpret_cast<float2*>(p) = make_float2(a, b);
}

// ---------------------------------------------------------------------------
// 1) CPE (half out) + src half copy + pool quarter-partials (no atomics)
// ---------------------------------------------------------------------------
__global__ __launch_bounds__(256) void k_cpe(const float* __restrict__ src,
                                             const float* __restrict__ cpe_w,
                                             __half* __restrict__ s,
                                             __half* __restrict__ srch,
                                             float* __restrict__ poolpart) {
    int gid = blockIdx.x * 256 + threadIdx.x;
    int p4 = gid * 4;
    int x = p4 & 63;
    int h = (p4 >> 6) & 63;
    int c = (p4 >> 12) & 127;
    const float* wp = cpe_w + c * 9;

    float a0 = 0.f, a1 = 0.f, a2 = 0.f, a3 = 0.f;
    float4 ctr = *reinterpret_cast<const float4*>(src + p4);

#pragma unroll
    for (int dy = -1; dy <= 1; dy++) {
        int hy = h + dy;
        if (hy < 0 || hy >= Hh) continue;
        const float* r = src + p4 + dy * Ww;
        float4 m = (dy == 0) ? ctr : *reinterpret_cast<const float4*>(r);
        float lft = (x > 0)  ? r[-1] : 0.f;
        float rgt = (x < 60) ? r[4]  : 0.f;
        float wl = wp[(dy + 1) * 3 + 0];
        float wc = wp[(dy + 1) * 3 + 1];
        float wr = wp[(dy + 1) * 3 + 2];
        a0 += wl * lft + wc * m.x + wr * m.y;
        a1 += wl * m.x + wc * m.y + wr * m.z;
        a2 += wl * m.y + wc * m.z + wr * m.w;
        a3 += wl * m.z + wc * m.w + wr * rgt;
    }
    __half2* sp = reinterpret_cast<__half2*>(s + p4);
    sp[0] = __floats2half2_rn(a0 + ctr.x, a1 + ctr.y);
    sp[1] = __floats2half2_rn(a2 + ctr.z, a3 + ctr.w);
    __half2* cph = reinterpret_cast<__half2*>(srch + p4);
    cph[0] = __floats2half2_rn(ctr.x, ctr.y);
    cph[1] = __floats2half2_rn(ctr.z, ctr.w);

    float psum = ctr.x + ctr.y + ctr.z + ctr.w;
    __shared__ float sm[256];
    sm[threadIdx.x] = psum;
    __syncthreads();
    for (int sstep = 128; sstep > 0; sstep >>= 1) {
        if (threadIdx.x < sstep) sm[threadIdx.x] += sm[threadIdx.x + sstep];
        __syncthreads();
    }
    if (threadIdx.x == 0) poolpart[blockIdx.x] = sm[0];   // [bc*4 + quarter]
}

// ---------------------------------------------------------------------------
// 2) fused wconv + ECA + w2b
// ---------------------------------------------------------------------------
__device__ __forceinline__ float poolsum(const float* pp, int pc) {
    return pp[pc * 4] + pp[pc * 4 + 1] + pp[pc * 4 + 2] + pp[pc * 4 + 3];
}

__global__ __launch_bounds__(256) void k_w2b(const float* __restrict__ qkv_w,
                                             const float* __restrict__ out_w,
                                             const float* __restrict__ poolpart,
                                             const float* __restrict__ conv1d_w,
                                             __half* __restrict__ wq,
                                             __half* __restrict__ w1,
                                             __half* __restrict__ w2b) {
    int idx = blockIdx.x * 256 + threadIdx.x;
    if (idx >= Bb * OUTC * Cc) return;
    // side job: weight conversions
    if (idx < 3 * Cc * Cc) wq[idx] = __float2half_rn(qkv_w[idx]);
    if (idx < OUTC * Cc) {
        int o = idx >> 7, c2 = idx & 127;
        w1[idx] = __float2half_rn(out_w[o * 256 + c2]);
    }
    int c = idx & 127;
    int o = (idx >> 7) & 511;
    int b = idx >> 16;
    int pc = (b << 7) + c;
    const float inv = 1.0f / HW;
    float left  = (c > 0)   ? poolsum(poolpart, pc - 1) * inv : 0.f;
    float mid   = poolsum(poolpart, pc) * inv;
    float right = (c < 127) ? poolsum(poolpart, pc + 1) * inv : 0.f;
    float z = conv1d_w[0] * left + conv1d_w[1] * mid + conv1d_w[2] * right;
    float ca = 1.0f / (1.0f + __expf(-z));
    w2b[idx] = __float2half_rn(out_w[o * 256 + 128 + c] * ca);
}

// ---------------------------------------------------------------------------
// 3) fp16 GEMM: BM=128, BN=128, BK=16, 8 warps (64x32 warp tile),
//    3-stage cp.async, ldmatrix, fp32 accum, 2 CTAs/SM.
// ---------------------------------------------------------------------------
template <int NPARTS, typename OutT>
__global__ __launch_bounds__(256, 2) void k_mma_gemm(
    const __half* __restrict__ A0, size_t sA0,
    const __half* __restrict__ B0, size_t sB0,
    const __half* __restrict__ A1, size_t sA1,
    const __half* __restrict__ B1, size_t sB1,
    OutT* __restrict__ C, size_t sC) {
    constexpr int BlkM = 128, BlkN = 128, BlkK = 16;
    constexpr int ASTh = 24;   // row stride (halves), ldmatrix conflict-free
    constexpr int BSTh = 136;  // row stride (halves), 272B ≡ 16 mod 128 -> conflict-free
    constexpr int ASZh = BlkM * ASTh;  // 3072
    constexpr int BSZh = BlkK * BSTh;  // 2176

    extern __shared__ __half smh[];
    __half* Asm = smh;
    __half* Bsm = smh + 3 * ASZh;
    const uint32_t a_base0 = (uint32_t)__cvta_generic_to_shared(Asm);
    const uint32_t b_base0 = (uint32_t)__cvta_generic_to_shared(Bsm);

    const int tid = threadIdx.x;
    const int bz = blockIdx.z, mtile = blockIdx.x, ntile = blockIdx.y;
    const int warp = tid >> 5, lane = tid & 31;
    const int g = lane >> 2, t = lane & 3;
    const int wm = (warp >> 2) * 64;   // 2 warp-rows of 64
    const int wn = (warp & 3) * 32;    // 4 warp-cols of 32

    auto load_chunk = [&](int cidx, int buf) {
        const int part = (NPARTS == 2) ? (cidx >> 3) : 0;
        const int kin = (cidx & 7) * BlkK;
        const __half* Aptr = part ? A1 + (size_t)bz * sA1 : A0 + (size_t)bz * sA0;
        const __half* Bptr = part ? B1 + (size_t)bz * sB1 : B0 + (size_t)bz * sB0;
        __half* Abuf = Asm + buf * ASZh;
        __half* Bbuf = Bsm + buf * BSZh;
        {   // A: 128 rows x 16 halves
            int row = tid >> 1, ho = (tid & 1) * 8;
            cp16((uint32_t)__cvta_generic_to_shared(&Abuf[row * ASTh + ho]),
                 Aptr + (size_t)(mtile * BlkM + row) * 128 + kin + ho);
        }
        {   // B: 16 rows x 128 halves
            int kk = tid >> 4, col = (tid & 15) * 8;
            cp16((uint32_t)__cvta_generic_to_shared(&Bbuf[kk * BSTh + col]),
                 Bptr + (size_t)(kin + kk) * HW + ntile * BlkN + col);
        }
        cp_commit();
    };

    float acc[4][4][4];
#pragma unroll
    for (int f = 0; f < 4; f++)
#pragma unroll
        for (int nf = 0; nf < 4; nf++)
#pragma unroll
            for (int j = 0; j < 4; j++) acc[f][nf][j] = 0.f;

    const int a_row_in = (lane & 7) + ((lane >> 3) & 1) * 8;
    const int a_kbase  = (lane >> 4) * 8;
    const int b_krow   = lane & 15;

    auto compute = [&](int buf) {
        const uint32_t a_base = a_base0 + buf * ASZh * 2;
        const uint32_t b_base = b_base0 + buf * BSZh * 2;
        uint32_t areg[4][4];
#pragma unroll
        for (int f = 0; f < 4; f++) {
            uint32_t addr = a_base +
                (uint32_t)(((wm + f * 16 + a_row_in) * ASTh + a_kbase) * 2);
            ldsm_x4(areg[f], addr);
        }
        uint32_t breg[4][2];
#pragma unroll
        for (int nf = 0; nf < 4; nf++) {
            uint32_t addr = b_base +
                (uint32_t)((b_krow * BSTh + wn + nf * 8) * 2);
            ldsm_x2t(breg[nf], addr);
        }
#pragma unroll
        for (int f = 0; f < 4; f++)
#pragma unroll
            for (int nf = 0; nf < 4; nf++)
                mma_f16(acc[f][nf], areg[f], breg[nf]);
    };

    const int NC = NPARTS * 8;
    load_chunk(0, 0);
    load_chunk(1, 1);
    for (int cidx = 0; cidx < NC; cidx++) {
        if (cidx < NC - 1) cp_wait<1>(); else cp_wait<0>();
        __syncthreads();
        if (cidx + 2 < NC) load_chunk(cidx + 2, (cidx + 2) % 3);
        compute(cidx % 3);
    }

    OutT* Cbase = C + (size_t)bz * sC + (size_t)(mtile * BlkM) * HW + ntile * BlkN;
#pragma unroll
    for (int f = 0; f < 4; f++) {
#pragma unroll
        for (int nf = 0; nf < 4; nf++) {
            int row = wm + f * 16 + g;
            int col = wn + nf * 8 + t * 2;
            store2(Cbase + (size_t)row * HW + col, acc[f][nf][0], acc[f][nf][1]);
            store2(Cbase + (size_t)(row + 8) * HW + col, acc[f][nf][2], acc[f][nf][3]);
        }
    }
}

// ---------------------------------------------------------------------------
// 4) softmax + lambda — no max pass (k values O(1); fp32 exp is safe)
// ---------------------------------------------------------------------------
__global__ __launch_bounds__(256) void k_softmax_lambda(const __half* __restrict__ qkv,
                                                        float* __restrict__ lambda) {
    const int bh = blockIdx.x;
    const int hlf = blockIdx.y;
    const int b = bh >> 3, nh = bh & 7;
    const __half* kbase = qkv + ((size_t)b * 384 + 128 + nh * 16) * HW;
    const __half* vbase = qkv + ((size_t)b * 384 + 256 + nh * 16) * HW;
    const int tid = threadIdx.x;
    const int warp = tid >> 5, lane = tid & 31;
    const int i = hlf * 8 + warp;
    const __half* krow = kbase + (size_t)i * HW;

    __shared__ float vsm[16][512];

    float acc[16];
#pragma unroll
    for (int o = 0; o < 16; o++) acc[o] = 0.f;
    float se = 0.f;

    for (int n0 = 0; n0 < HW; n0 += 512) {
        __syncthreads();
        for (int t2 = tid; t2 < 16 * 256; t2 += 256) {
            int o = t2 >> 8, n2 = (t2 & 255) * 2;
            __half2 hv = *reinterpret_cast<const __half2*>(vbase + (size_t)o * HW + n0 + n2);
            vsm[o][n2]     = __low2float(hv);
            vsm[o][n2 + 1] = __high2float(hv);
        }
        __syncthreads();
#pragma unroll 4
        for (int n = lane; n < 512; n += 32) {
            float e = __expf(__half2float(krow[n0 + n]));
            se += e;
#pragma unroll
            for (int o = 0; o < 16; o++) acc[o] += e * vsm[o][n];
        }
    }

#pragma unroll
    for (int off = 16; off > 0; off >>= 1) {
        se += __shfl_xor_sync(0xffffffff, se, off);
#pragma unroll
        for (int o = 0; o < 16; o++)
            acc[o] += __shfl_xor_sync(0xffffffff, acc[o], off);
    }
    if (lane == 0) {
        float inv = 0.25f / se;
        float* lp = lambda + (size_t)bh * 256 + i * 16;
#pragma unroll
        for (int o = 0; o < 16; o++) lp[o] = acc[o] * inv;
    }
}

// ---------------------------------------------------------------------------
// 5) result1 = content + q * position_lambda (half in/out)
// ---------------------------------------------------------------------------
__global__ __launch_bounds__(256) void k_result1(const __half* __restrict__ qkv,
                                                 const float* __restrict__ lambda,
                                                 const float* __restrict__ rel_pos,
                                                 __half* __restrict__ r1) {
    const int bh = blockIdx.z;
    const int b = bh >> 3, nh = bh & 7;
    const int x0 = blockIdx.x * 16, y0 = blockIdx.y * 16;
    const int tid = threadIdx.x;
    const int px = tid & 15, py = tid >> 4;

    __shared__ float lam[16][16];
    __shared__ float relw[16][25];
    __shared__ float qs[16][16][16];
    __shared__ float vs[16][20][20];

    lam[py][px] = lambda[((size_t)bh * 16 + py) * 16 + px];
    for (int t = tid; t < 400; t += 256) relw[t / 25][t % 25] = rel_pos[t];
    const __half* qbase = qkv + ((size_t)b * 384 + nh * 16) * HW;
#pragma unroll
    for (int ch = 0; ch < 16; ch++)
        qs[ch][py][px] = __half2float(qbase[(size_t)ch * HW + (y0 + py) * Ww + x0 + px]);
    const __half* vbase = qkv + ((size_t)b * 384 + 256 + nh * 16) * HW;
    for (int t = tid; t < 6400; t += 256) {
        int ch = t / 400;
        int r = t % 400;
        int vy = r / 20, vx = r % 20;
        int gy = y0 + vy - 2, gx = x0 + vx - 2;
        float val = 0.f;
        if (gy >= 0 && gy < Hh && gx >= 0 && gx < Ww)
            val = __half2float(vbase[(size_t)ch * HW + gy * Ww + gx]);
        vs[ch][vy][vx] = val;
    }
    __syncthreads();

    __half* obase = r1 + ((size_t)b * Cc + nh * 16) * HW + (y0 + py) * Ww + x0 + px;
#pragma unroll
    for (int o = 0; o < 16; o++) {
        float content = 0.f;
#pragma unroll
        for (int i = 0; i < 16; i++) content += qs[i][py][px] * lam[i][o];
        float pos = 0.f;
#pragma unroll
        for (int ky = 0; ky < 5; ky++)
#pragma unroll
            for (int kx = 0; kx < 5; kx++)
                pos += relw[o][ky * 5 + kx] * vs[o][py + ky][px + kx];
        obase[(size_t)o * HW] = __float2half_rn(content + qs[o][py][px] * pos);
    }
}

// ---------------------------------------------------------------------------
// Launch
// ---------------------------------------------------------------------------
extern "C" void kernel_launch(void* const* d_in, const int* in_sizes, int n_in,
                              void* d_out, int out_size) {
    const float* src      = (const float*)d_in[0];
    const float* cpe_w    = (const float*)d_in[1];
    const float* qkv_w    = (const float*)d_in[2];
    const float* rel_pos  = (const float*)d_in[3];
    const float* conv1d_w = (const float*)d_in[4];
    const float* out_w    = (const float*)d_in[5];
    float* out = (float*)d_out;

    __half *s_p, *srch_p, *qkv_p, *w2b_p, *r1_p, *wq_p, *w1_p;
    float *lam_p, *pp_p;
    cudaGetSymbolAddress((void**)&s_p,    g_s);
    cudaGetSymbolAddress((void**)&srch_p, g_srch);
    cudaGetSymbolAddress((void**)&qkv_p,  g_qkv);
    cudaGetSymbolAddress((void**)&lam_p,  g_lambda);
    cudaGetSymbolAddress((void**)&pp_p,   g_poolpart);
    cudaGetSymbolAddress((void**)&w2b_p,  g_w2b);
    cudaGetSymbolAddress((void**)&r1_p,   g_r1);
    cudaGetSymbolAddress((void**)&wq_p,   g_wq);
    cudaGetSymbolAddress((void**)&w1_p,   g_w1);

    const int gemm_smem = 3 * (128 * 24 + 16 * 136) * 2;  // 31488 bytes
    cudaFuncSetAttribute(k_mma_gemm<1, __half>, cudaFuncAttributeMaxDynamicSharedMemorySize, gemm_smem);
    cudaFuncSetAttribute(k_mma_gemm<2, float>,  cudaFuncAttributeMaxDynamicSharedMemorySize, gemm_smem);

    k_cpe<<<Bb * Cc * HW / 1024, 256>>>(src, cpe_w, s_p, srch_p, pp_p);
    k_w2b<<<(Bb * OUTC * Cc + 255) / 256, 256>>>(qkv_w, out_w, pp_p, conv1d_w,
                                                 wq_p, w1_p, w2b_p);
    {
        dim3 grid(3 * Cc / 128, HW / 128, Bb);
        k_mma_gemm<1, __half><<<grid, 256, gemm_smem>>>(wq_p, 0,
                                                        s_p, (size_t)Cc * HW,
                                                        nullptr, 0, nullptr, 0,
                                                        qkv_p, (size_t)3 * Cc * HW);
    }
    {
        dim3 grid(Bb * NHh, 2);
        k_softmax_lambda<<<grid, 256>>>(qkv_p, lam_p);
    }
    {
        dim3 grid(Ww / 16, Hh / 16, Bb * NHh);
        k_result1<<<grid, 256>>>(qkv_p, lam_p, rel_pos, r1_p);
    }
    {
        dim3 grid(OUTC / 128, HW / 128, Bb);
        k_mma_gemm<2, float><<<grid, 256, gemm_smem>>>(w1_p, 0,
                                                       r1_p, (size_t)Cc * HW,
                                                       w2b_p, (size_t)OUTC * Cc,
                                                       srch_p, (size_t)Cc * HW,
                                                       out, (size_t)OUTC * HW);
    }
}